// round 2
// baseline (speedup 1.0000x reference)
#include <cuda_runtime.h>
#include <math.h>

#define BB 32
#define PP 2048
#define KK 16
#define NH 128

// Scratch (no allocations allowed) — ~100MB of device globals.
__device__ int   g_nbr[BB * PP * KK];
__device__ float g_h1[BB * PP * NH];
__device__ float g_t [BB * PP * NH];
__device__ float g_h2[BB * PP * NH];

// ---------------------------------------------------------------------------
// KNN: per batch, 16 nearest (incl. self) by d2 = sq_i + sq_j - 2*dot.
// Ties broken by lower index (matches jax.lax.top_k stability).
// ---------------------------------------------------------------------------
__global__ void knn_kernel(const float* __restrict__ pos) {
    const int b   = blockIdx.y;
    const int q   = blockIdx.x * blockDim.x + threadIdx.x;
    const float* pb = pos + (size_t)b * PP * 3;

    const float qx = pb[q * 3 + 0];
    const float qy = pb[q * 3 + 1];
    const float qz = pb[q * 3 + 2];
    const float qsq = qx * qx + qy * qy + qz * qz;

    float kd[KK];
    int   ki[KK];
#pragma unroll
    for (int s = 0; s < KK; ++s) { kd[s] = 3.4e38f; ki[s] = -1; }

    __shared__ float4 tile[128];

    for (int t0 = 0; t0 < PP; t0 += 128) {
        const int j = t0 + threadIdx.x;
        const float x = pb[j * 3 + 0];
        const float y = pb[j * 3 + 1];
        const float z = pb[j * 3 + 2];
        tile[threadIdx.x] = make_float4(x, y, z, x * x + y * y + z * z);
        __syncthreads();

#pragma unroll 4
        for (int jj = 0; jj < 128; ++jj) {
            const float4 c = tile[jj];
            const float dot = qx * c.x + qy * c.y + qz * c.z;
            const float d2  = (qsq + c.w) - 2.0f * dot;
            if (d2 < kd[KK - 1]) {
                kd[KK - 1] = d2;
                ki[KK - 1] = t0 + jj;
#pragma unroll
                for (int s = KK - 1; s > 0; --s) {
                    if (kd[s] < kd[s - 1]) {
                        const float td = kd[s]; kd[s] = kd[s - 1]; kd[s - 1] = td;
                        const int   ti = ki[s]; ki[s] = ki[s - 1]; ki[s - 1] = ti;
                    }
                }
            }
        }
        __syncthreads();
    }

    const int base = (b * PP + q) * KK;
#pragma unroll
    for (int s = 0; s < KK; ++s) g_nbr[base + s] = ki[s];
}

// ---------------------------------------------------------------------------
// Unified layer kernel.
//  MODE 0: t-precompute:  g_t[r] = g_h1[r] @ Wb + bo          (16 rows/block)
//  MODE 1: layer 1:       g_h1[p] = relu(max_k(relu(m@Wsm+bh) @ Wb) + bo)
//  MODE 2: layer 2:       g_h2[p] = relu(max_k(relu(t_j + rel@Wsm) @ Wb) + bo)
// 128 threads; thread owns output dim d = tid with 16 accumulators (edges/rows).
// ---------------------------------------------------------------------------
template <int MODE>
__global__ __launch_bounds__(128) void layer_kernel(
    const float* __restrict__ pos,
    const float* __restrict__ Wsmall,   // MODE1: W1a[6,128]; MODE2: W2a rows 128..130
    const float* __restrict__ bh,       // MODE1: b1a
    const float* __restrict__ Wb,       // [128,128] second-linear weights
    const float* __restrict__ bo)       // out bias
{
    __shared__ __align__(16) float hid[16][NH];
    __shared__ float sM[16][8];
    __shared__ int   sJ[16];

    const int tid = threadIdx.x;

    const float* src = (MODE == 0) ? g_h1 : g_t;
    float*       dst = (MODE == 0) ? g_t : ((MODE == 1) ? g_h1 : g_h2);

    if (MODE == 0) {
        const int row0 = blockIdx.x * 16;
#pragma unroll
        for (int k = 0; k < 16; ++k)
            hid[k][tid] = src[(size_t)(row0 + k) * NH + tid];
        __syncthreads();

        float acc[16];
#pragma unroll
        for (int k = 0; k < 16; ++k) acc[k] = 0.0f;

#pragma unroll 4
        for (int c = 0; c < NH; c += 4) {
            const float w0 = Wb[(c + 0) * NH + tid];
            const float w1 = Wb[(c + 1) * NH + tid];
            const float w2 = Wb[(c + 2) * NH + tid];
            const float w3 = Wb[(c + 3) * NH + tid];
#pragma unroll
            for (int k = 0; k < 16; ++k) {
                const float4 h4 = *(const float4*)&hid[k][c];
                acc[k] = fmaf(h4.x, w0, acc[k]);
                acc[k] = fmaf(h4.y, w1, acc[k]);
                acc[k] = fmaf(h4.z, w2, acc[k]);
                acc[k] = fmaf(h4.w, w3, acc[k]);
            }
        }
        const float bv = bo[tid];
#pragma unroll
        for (int k = 0; k < 16; ++k)
            dst[(size_t)(row0 + k) * NH + tid] = acc[k] + bv;
        return;
    }

    // MODE 1 / 2 : 8 points per block, sequential.
    const int p0 = blockIdx.x * 8;
    const float bhv = (MODE == 1) ? bh[tid] : 0.0f;
    const float bov = bo[tid];

    float wsm[6];
    const int NSM = (MODE == 1) ? 6 : 3;
#pragma unroll
    for (int u = 0; u < 6; ++u)
        wsm[u] = (u < NSM) ? Wsmall[u * NH + tid] : 0.0f;

    for (int pi = 0; pi < 8; ++pi) {
        const int p = p0 + pi;               // global point index
        if (tid < 16) {
            const int b  = p / PP;
            const int jl = g_nbr[p * KK + tid];   // local neighbor idx
            const int jg = b * PP + jl;
            sJ[tid] = jg;
            const float pjx = pos[(size_t)jg * 3 + 0];
            const float pjy = pos[(size_t)jg * 3 + 1];
            const float pjz = pos[(size_t)jg * 3 + 2];
            const float pix = pos[(size_t)p * 3 + 0];
            const float piy = pos[(size_t)p * 3 + 1];
            const float piz = pos[(size_t)p * 3 + 2];
            if (MODE == 1) {
                sM[tid][0] = pjx; sM[tid][1] = pjy; sM[tid][2] = pjz;
                sM[tid][3] = pjx - pix; sM[tid][4] = pjy - piy; sM[tid][5] = pjz - piz;
            } else {
                sM[tid][0] = pjx - pix; sM[tid][1] = pjy - piy; sM[tid][2] = pjz - piz;
            }
        }
        __syncthreads();

        // Stage A: hidden activations for the 16 edges (thread = hidden dim).
#pragma unroll
        for (int k = 0; k < 16; ++k) {
            float h;
            if (MODE == 1) {
                h = bhv;
#pragma unroll
                for (int u = 0; u < 6; ++u) h = fmaf(sM[k][u], wsm[u], h);
            } else {
                h = src[(size_t)sJ[k] * NH + tid];   // t_j (includes b2a)
#pragma unroll
                for (int u = 0; u < 3; ++u) h = fmaf(sM[k][u], wsm[u], h);
            }
            hid[k][tid] = fmaxf(h, 0.0f);
        }
        __syncthreads();

        // Stage B: [16,128] x [128,128] with per-edge accumulators, max at end.
        float acc[16];
#pragma unroll
        for (int k = 0; k < 16; ++k) acc[k] = 0.0f;

#pragma unroll 4
        for (int c = 0; c < NH; c += 4) {
            const float w0 = Wb[(c + 0) * NH + tid];
            const float w1 = Wb[(c + 1) * NH + tid];
            const float w2 = Wb[(c + 2) * NH + tid];
            const float w3 = Wb[(c + 3) * NH + tid];
#pragma unroll
            for (int k = 0; k < 16; ++k) {
                const float4 h4 = *(const float4*)&hid[k][c];
                acc[k] = fmaf(h4.x, w0, acc[k]);
                acc[k] = fmaf(h4.y, w1, acc[k]);
                acc[k] = fmaf(h4.z, w2, acc[k]);
                acc[k] = fmaf(h4.w, w3, acc[k]);
            }
        }

        float m = acc[0];
#pragma unroll
        for (int k = 1; k < 16; ++k) m = fmaxf(m, acc[k]);
        dst[(size_t)p * NH + tid] = fmaxf(m + bov, 0.0f);
        __syncthreads();
    }
}

// ---------------------------------------------------------------------------
// Global max pool + classifier: out[b] = max_p(h2[b,p,:]) @ Wc + bc
// ---------------------------------------------------------------------------
__global__ void pool_kernel(const float* __restrict__ Wc,
                            const float* __restrict__ bc,
                            float* __restrict__ out) {
    const int b   = blockIdx.x;
    const int tid = threadIdx.x;
    const float* hb = g_h2 + (size_t)b * PP * NH;

    float m0 = -3.4e38f, m1 = m0, m2 = m0, m3 = m0;
    for (int p = 0; p < PP; p += 4) {
        m0 = fmaxf(m0, hb[(size_t)(p + 0) * NH + tid]);
        m1 = fmaxf(m1, hb[(size_t)(p + 1) * NH + tid]);
        m2 = fmaxf(m2, hb[(size_t)(p + 2) * NH + tid]);
        m3 = fmaxf(m3, hb[(size_t)(p + 3) * NH + tid]);
    }
    __shared__ float sg[NH];
    sg[tid] = fmaxf(fmaxf(m0, m1), fmaxf(m2, m3));
    __syncthreads();

    if (tid < 10) {
        float a = bc[tid];
#pragma unroll 8
        for (int d = 0; d < NH; ++d) a = fmaf(sg[d], Wc[d * 10 + tid], a);
        out[b * 10 + tid] = a;
    }
}

// ---------------------------------------------------------------------------
extern "C" void kernel_launch(void* const* d_in, const int* in_sizes, int n_in,
                              void* d_out, int out_size) {
    const float* pos = (const float*)d_in[0];
    // d_in[1] = batch (sorted, equal-size graphs) — unused
    const float* W1a = (const float*)d_in[2];
    const float* b1a = (const float*)d_in[3];
    const float* W1b = (const float*)d_in[4];
    const float* b1b = (const float*)d_in[5];
    const float* W2a = (const float*)d_in[6];
    const float* b2a = (const float*)d_in[7];
    const float* W2b = (const float*)d_in[8];
    const float* b2b = (const float*)d_in[9];
    const float* Wc  = (const float*)d_in[10];
    const float* bc  = (const float*)d_in[11];
    float* out = (float*)d_out;

    // 1) KNN graph
    knn_kernel<<<dim3(PP / 128, BB), 128>>>(pos);

    // 2) Layer 1 (edge conv on positions) -> g_h1
    layer_kernel<1><<<BB * PP / 8, 128>>>(pos, W1a, b1a, W1b, b1b);

    // 3) t_j = h1_j @ W2a[0:128] + b2a   (per-node hoist of layer-2 first linear)
    layer_kernel<0><<<BB * PP / 16, 128>>>(pos, nullptr, nullptr, W2a, b2a);

    // 4) Layer 2 (edge conv on features) -> g_h2
    layer_kernel<2><<<BB * PP / 8, 128>>>(pos, W2a + 128 * NH, nullptr, W2b, b2b);

    // 5) Global max pool + classifier
    pool_kernel<<<BB, 128>>>(Wc, bc, out);
}

// round 3
// speedup vs baseline: 1.2325x; 1.2325x over previous
#include <cuda_runtime.h>
#include <math.h>

#define BB 32
#define PP 2048
#define KK 16
#define NH 128

typedef unsigned long long u64;

// Scratch (no allocations allowed).
__device__ int   g_nbr[BB * PP * KK];
__device__ float g_h1[BB * PP * NH];
__device__ float g_t [BB * PP * NH];
__device__ float g_h2[BB * PP * NH];

// ---- packed f32x2 helpers --------------------------------------------------
__device__ __forceinline__ u64 pack_dup(float v) {
    u64 r; asm("mov.b64 %0, {%1, %1};" : "=l"(r) : "f"(v)); return r;
}
__device__ __forceinline__ u64 ffma2(u64 a, u64 b, u64 c) {
    u64 d; asm("fma.rn.f32x2 %0, %1, %2, %3;" : "=l"(d) : "l"(a), "l"(b), "l"(c));
    return d;
}
__device__ __forceinline__ float2 unpack2(u64 v) {
    float2 f; asm("mov.b64 {%0, %1}, %2;" : "=f"(f.x), "=f"(f.y) : "l"(v));
    return f;
}

// ---------------------------------------------------------------------------
// KNN: per batch, 16 nearest (incl. self). Ties -> lower index (top_k order).
// ---------------------------------------------------------------------------
__global__ void knn_kernel(const float* __restrict__ pos) {
    const int b = blockIdx.y;
    const int q = blockIdx.x * blockDim.x + threadIdx.x;
    const float* pb = pos + (size_t)b * PP * 3;

    const float qx = pb[q * 3 + 0];
    const float qy = pb[q * 3 + 1];
    const float qz = pb[q * 3 + 2];
    const float qsq = qx * qx + qy * qy + qz * qz;

    float kd[KK];
    int   ki[KK];
#pragma unroll
    for (int s = 0; s < KK; ++s) { kd[s] = 3.4e38f; ki[s] = -1; }

    __shared__ float4 tile[128];

    for (int t0 = 0; t0 < PP; t0 += 128) {
        const int j = t0 + threadIdx.x;
        const float x = pb[j * 3 + 0];
        const float y = pb[j * 3 + 1];
        const float z = pb[j * 3 + 2];
        tile[threadIdx.x] = make_float4(x, y, z, x * x + y * y + z * z);
        __syncthreads();

#pragma unroll 4
        for (int jj = 0; jj < 128; ++jj) {
            const float4 c = tile[jj];
            const float dot = qx * c.x + qy * c.y + qz * c.z;
            const float d2  = (qsq + c.w) - 2.0f * dot;
            if (d2 < kd[KK - 1]) {
                kd[KK - 1] = d2;
                ki[KK - 1] = t0 + jj;
#pragma unroll
                for (int s = KK - 1; s > 0; --s) {
                    if (kd[s] < kd[s - 1]) {
                        const float td = kd[s]; kd[s] = kd[s - 1]; kd[s - 1] = td;
                        const int   ti = ki[s]; ki[s] = ki[s - 1]; ki[s - 1] = ti;
                    }
                }
            }
        }
        __syncthreads();
    }

    const int base = (b * PP + q) * KK;
#pragma unroll
    for (int s = 0; s < KK; ++s) g_nbr[base + s] = ki[s];
}

// ---------------------------------------------------------------------------
// Edge-conv layer (MODE 1: layer 1 on positions, MODE 2: layer 2 on features).
// Block = 128 threads = 4 warps; warp w handles point p0+w.
// GEMM: lane l owns output dims 4l..4l+3 as two f32x2 pairs; 16 edge accs.
// ---------------------------------------------------------------------------
template <int MODE>
__global__ __launch_bounds__(128) void layer_kernel(
    const float* __restrict__ pos,
    const float* __restrict__ Wsmall,   // MODE1: W1a[6,128]; MODE2: W2a rows 128..130
    const float* __restrict__ bh,       // MODE1: b1a
    const float* __restrict__ Wb,       // [128,128]
    const float* __restrict__ bo)       // out bias
{
    __shared__ __align__(16) float hid[4][KK][NH];   // 32 KB
    __shared__ float sM[4][KK][8];
    __shared__ int   sJ[4][KK];

    const int tid = threadIdx.x;
    const int wid = tid >> 5;
    const int lid = tid & 31;
    const int p0  = blockIdx.x * 4;

    const float* src = g_t;
    float*       dst = (MODE == 1) ? g_h1 : g_h2;

    // --- neighbor / relative-position prep (64 threads: 4 pts x 16 edges) ---
    if (tid < 64) {
        const int pt = tid >> 4;
        const int k  = tid & 15;
        const int p  = p0 + pt;
        const int b  = p / PP;
        const int jl = g_nbr[p * KK + k];
        const int jg = b * PP + jl;
        sJ[pt][k] = jg;
        const float pjx = pos[(size_t)jg * 3 + 0];
        const float pjy = pos[(size_t)jg * 3 + 1];
        const float pjz = pos[(size_t)jg * 3 + 2];
        const float pix = pos[(size_t)p * 3 + 0];
        const float piy = pos[(size_t)p * 3 + 1];
        const float piz = pos[(size_t)p * 3 + 2];
        if (MODE == 1) {
            sM[pt][k][0] = pjx; sM[pt][k][1] = pjy; sM[pt][k][2] = pjz;
            sM[pt][k][3] = pjx - pix; sM[pt][k][4] = pjy - piy; sM[pt][k][5] = pjz - piz;
        } else {
            sM[pt][k][0] = pjx - pix; sM[pt][k][1] = pjy - piy; sM[pt][k][2] = pjz - piz;
        }
    }

    // small-weight column for this thread's hidden dim (stage A: thread = dim)
    float wsm[6];
    const int NSM = (MODE == 1) ? 6 : 3;
#pragma unroll
    for (int u = 0; u < 6; ++u)
        wsm[u] = (u < NSM) ? Wsmall[u * NH + tid] : 0.0f;
    const float bhv = (MODE == 1) ? bh[tid] : 0.0f;
    __syncthreads();

    // --- Stage A: hidden activations for all 4 points x 16 edges ------------
#pragma unroll
    for (int pt = 0; pt < 4; ++pt) {
#pragma unroll
        for (int k = 0; k < KK; ++k) {
            float h;
            if (MODE == 1) {
                h = bhv;
#pragma unroll
                for (int u = 0; u < 6; ++u) h = fmaf(sM[pt][k][u], wsm[u], h);
            } else {
                h = src[(size_t)sJ[pt][k] * NH + tid];   // t_j (includes b2a)
#pragma unroll
                for (int u = 0; u < 3; ++u) h = fmaf(sM[pt][k][u], wsm[u], h);
            }
            hid[pt][k][tid] = fmaxf(h, 0.0f);
        }
    }
    __syncthreads();

    // --- Stage B: warp-per-point GEMM [16,128]x[128,128], f32x2 packed ------
    const int pt = wid;
    const int d0 = lid * 4;

    u64 acc[KK][2];
#pragma unroll
    for (int k = 0; k < KK; ++k) { acc[k][0] = 0ULL; acc[k][1] = 0ULL; }

#pragma unroll 2
    for (int c = 0; c < NH; c += 4) {
        // weight pairs for this lane's 4 dims, 4 columns (bit-reinterpret f32x2)
        const ulonglong2 wa = *(const ulonglong2*)&Wb[(c + 0) * NH + d0];
        const ulonglong2 wb2 = *(const ulonglong2*)&Wb[(c + 1) * NH + d0];
        const ulonglong2 wc2 = *(const ulonglong2*)&Wb[(c + 2) * NH + d0];
        const ulonglong2 wd2 = *(const ulonglong2*)&Wb[(c + 3) * NH + d0];
#pragma unroll
        for (int k = 0; k < KK; ++k) {
            const float4 h4 = *(const float4*)&hid[pt][k][c];
            const u64 h0 = pack_dup(h4.x);
            const u64 h1 = pack_dup(h4.y);
            const u64 h2 = pack_dup(h4.z);
            const u64 h3 = pack_dup(h4.w);
            acc[k][0] = ffma2(h0, wa.x,  acc[k][0]);
            acc[k][1] = ffma2(h0, wa.y,  acc[k][1]);
            acc[k][0] = ffma2(h1, wb2.x, acc[k][0]);
            acc[k][1] = ffma2(h1, wb2.y, acc[k][1]);
            acc[k][0] = ffma2(h2, wc2.x, acc[k][0]);
            acc[k][1] = ffma2(h2, wc2.y, acc[k][1]);
            acc[k][0] = ffma2(h3, wd2.x, acc[k][0]);
            acc[k][1] = ffma2(h3, wd2.y, acc[k][1]);
        }
    }

    // max over edges, bias, relu, store
    float m0 = -3.4e38f, m1 = m0, m2 = m0, m3 = m0;
#pragma unroll
    for (int k = 0; k < KK; ++k) {
        const float2 f0 = unpack2(acc[k][0]);
        const float2 f1 = unpack2(acc[k][1]);
        m0 = fmaxf(m0, f0.x); m1 = fmaxf(m1, f0.y);
        m2 = fmaxf(m2, f1.x); m3 = fmaxf(m3, f1.y);
    }
    const float4 bv = *(const float4*)&bo[d0];
    float4 o;
    o.x = fmaxf(m0 + bv.x, 0.0f);
    o.y = fmaxf(m1 + bv.y, 0.0f);
    o.z = fmaxf(m2 + bv.z, 0.0f);
    o.w = fmaxf(m3 + bv.w, 0.0f);
    *(float4*)&dst[(size_t)(p0 + pt) * NH + d0] = o;
}

// ---------------------------------------------------------------------------
// t-precompute: g_t[r] = g_h1[r] @ W2a[0:128] + b2a. Block = 16 rows.
// Warp handles 4 rows; lane owns 4 dims (two f32x2 pairs).
// ---------------------------------------------------------------------------
__global__ __launch_bounds__(128) void tprep_kernel(
    const float* __restrict__ Wb,   // W2a[0:128,128]
    const float* __restrict__ bo)   // b2a
{
    __shared__ __align__(16) float hid[16][NH];   // 8 KB
    const int tid = threadIdx.x;
    const int wid = tid >> 5;
    const int lid = tid & 31;
    const int row0 = blockIdx.x * 16;

#pragma unroll
    for (int r = 0; r < 16; ++r)
        hid[r][tid] = g_h1[(size_t)(row0 + r) * NH + tid];
    __syncthreads();

    const int rb = wid * 4;      // this warp's 4 rows
    const int d0 = lid * 4;

    u64 acc[4][2];
#pragma unroll
    for (int r = 0; r < 4; ++r) { acc[r][0] = 0ULL; acc[r][1] = 0ULL; }

#pragma unroll 2
    for (int c = 0; c < NH; c += 4) {
        const ulonglong2 wa = *(const ulonglong2*)&Wb[(c + 0) * NH + d0];
        const ulonglong2 wb2 = *(const ulonglong2*)&Wb[(c + 1) * NH + d0];
        const ulonglong2 wc2 = *(const ulonglong2*)&Wb[(c + 2) * NH + d0];
        const ulonglong2 wd2 = *(const ulonglong2*)&Wb[(c + 3) * NH + d0];
#pragma unroll
        for (int r = 0; r < 4; ++r) {
            const float4 h4 = *(const float4*)&hid[rb + r][c];
            const u64 h0 = pack_dup(h4.x);
            const u64 h1 = pack_dup(h4.y);
            const u64 h2 = pack_dup(h4.z);
            const u64 h3 = pack_dup(h4.w);
            acc[r][0] = ffma2(h0, wa.x,  acc[r][0]);
            acc[r][1] = ffma2(h0, wa.y,  acc[r][1]);
            acc[r][0] = ffma2(h1, wb2.x, acc[r][0]);
            acc[r][1] = ffma2(h1, wb2.y, acc[r][1]);
            acc[r][0] = ffma2(h2, wc2.x, acc[r][0]);
            acc[r][1] = ffma2(h2, wc2.y, acc[r][1]);
            acc[r][0] = ffma2(h3, wd2.x, acc[r][0]);
            acc[r][1] = ffma2(h3, wd2.y, acc[r][1]);
        }
    }

    const float4 bv = *(const float4*)&bo[d0];
#pragma unroll
    for (int r = 0; r < 4; ++r) {
        const float2 f0 = unpack2(acc[r][0]);
        const float2 f1 = unpack2(acc[r][1]);
        float4 o;
        o.x = f0.x + bv.x; o.y = f0.y + bv.y;
        o.z = f1.x + bv.z; o.w = f1.y + bv.w;
        *(float4*)&g_t[(size_t)(row0 + rb + r) * NH + d0] = o;
    }
}

// ---------------------------------------------------------------------------
// Global max pool + classifier: out[b] = max_p(h2[b,p,:]) @ Wc + bc
// ---------------------------------------------------------------------------
__global__ void pool_kernel(const float* __restrict__ Wc,
                            const float* __restrict__ bc,
                            float* __restrict__ out) {
    const int b   = blockIdx.x;
    const int tid = threadIdx.x;
    const float* hb = g_h2 + (size_t)b * PP * NH;

    float m0 = -3.4e38f, m1 = m0, m2 = m0, m3 = m0;
    for (int p = 0; p < PP; p += 4) {
        m0 = fmaxf(m0, hb[(size_t)(p + 0) * NH + tid]);
        m1 = fmaxf(m1, hb[(size_t)(p + 1) * NH + tid]);
        m2 = fmaxf(m2, hb[(size_t)(p + 2) * NH + tid]);
        m3 = fmaxf(m3, hb[(size_t)(p + 3) * NH + tid]);
    }
    __shared__ float sg[NH];
    sg[tid] = fmaxf(fmaxf(m0, m1), fmaxf(m2, m3));
    __syncthreads();

    if (tid < 10) {
        float a = bc[tid];
#pragma unroll 8
        for (int d = 0; d < NH; ++d) a = fmaf(sg[d], Wc[d * 10 + tid], a);
        out[b * 10 + tid] = a;
    }
}

// ---------------------------------------------------------------------------
extern "C" void kernel_launch(void* const* d_in, const int* in_sizes, int n_in,
                              void* d_out, int out_size) {
    const float* pos = (const float*)d_in[0];
    const float* W1a = (const float*)d_in[2];
    const float* b1a = (const float*)d_in[3];
    const float* W1b = (const float*)d_in[4];
    const float* b1b = (const float*)d_in[5];
    const float* W2a = (const float*)d_in[6];
    const float* b2a = (const float*)d_in[7];
    const float* W2b = (const float*)d_in[8];
    const float* b2b = (const float*)d_in[9];
    const float* Wc  = (const float*)d_in[10];
    const float* bc  = (const float*)d_in[11];
    float* out = (float*)d_out;

    knn_kernel<<<dim3(PP / 128, BB), 128>>>(pos);
    layer_kernel<1><<<BB * PP / 4, 128>>>(pos, W1a, b1a, W1b, b1b);
    tprep_kernel<<<BB * PP / 16, 128>>>(W2a, b2a);
    layer_kernel<2><<<BB * PP / 4, 128>>>(pos, W2a + 128 * NH, nullptr, W2b, b2b);
    pool_kernel<<<BB, 128>>>(Wc, bc, out);
}

// round 6
// speedup vs baseline: 1.7193x; 1.3949x over previous
#include <cuda_runtime.h>
#include <cuda_bf16.h>
#include <math.h>
#include <stdint.h>

#define BB 32
#define PP 2048
#define KK 16
#define NH 128

typedef unsigned long long u64;

// Scratch (no allocations allowed).
__device__ int   g_nbr[BB * PP * KK];
__device__ float g_h1[BB * PP * NH];
__device__ float g_t [BB * PP * NH];
__device__ float g_h2[BB * PP * NH];
// Weight B-fragments in mma register order: [layer][(nt*8+kc)*32+lane] -> uint2{b0,b1}
__device__ uint2 g_wfh[2][16 * 8 * 32];
__device__ uint2 g_wfl[2][16 * 8 * 32];

// ---- helpers ---------------------------------------------------------------
__device__ __forceinline__ uint32_t smem_u32(const void* p) {
    return (uint32_t)__cvta_generic_to_shared(p);
}
__device__ __forceinline__ u64 pack_dup(float v) {
    u64 r; asm("mov.b64 %0, {%1, %1};" : "=l"(r) : "f"(v)); return r;
}
__device__ __forceinline__ u64 ffma2(u64 a, u64 b, u64 c) {
    u64 d; asm("fma.rn.f32x2 %0, %1, %2, %3;" : "=l"(d) : "l"(a), "l"(b), "l"(c));
    return d;
}
__device__ __forceinline__ float2 unpack2(u64 v) {
    float2 f; asm("mov.b64 {%0, %1}, %2;" : "=f"(f.x), "=f"(f.y) : "l"(v));
    return f;
}
__device__ __forceinline__ uint32_t pack_bf2(float a, float b) {
    return (uint32_t)__bfloat16_as_ushort(__float2bfloat16(a)) |
           ((uint32_t)__bfloat16_as_ushort(__float2bfloat16(b)) << 16);
}

__device__ __forceinline__ void ldsm_x4(uint32_t* r, uint32_t addr) {
    asm volatile("ldmatrix.sync.aligned.m8n8.x4.shared.b16 {%0,%1,%2,%3}, [%4];"
                 : "=r"(r[0]), "=r"(r[1]), "=r"(r[2]), "=r"(r[3]) : "r"(addr));
}
__device__ __forceinline__ void mma_bf16(float* d, const uint32_t* a, uint2 b) {
    asm volatile(
        "mma.sync.aligned.m16n8k16.row.col.f32.bf16.bf16.f32 "
        "{%0,%1,%2,%3}, {%4,%5,%6,%7}, {%8,%9}, {%0,%1,%2,%3};"
        : "+f"(d[0]), "+f"(d[1]), "+f"(d[2]), "+f"(d[3])
        : "r"(a[0]), "r"(a[1]), "r"(a[2]), "r"(a[3]), "r"(b.x), "r"(b.y));
}

// ---------------------------------------------------------------------------
// KNN (unchanged, known-correct)
// ---------------------------------------------------------------------------
__global__ void knn_kernel(const float* __restrict__ pos) {
    const int b = blockIdx.y;
    const int q = blockIdx.x * blockDim.x + threadIdx.x;
    const float* pb = pos + (size_t)b * PP * 3;

    const float qx = pb[q * 3 + 0];
    const float qy = pb[q * 3 + 1];
    const float qz = pb[q * 3 + 2];
    const float qsq = qx * qx + qy * qy + qz * qz;

    float kd[KK];
    int   ki[KK];
#pragma unroll
    for (int s = 0; s < KK; ++s) { kd[s] = 3.4e38f; ki[s] = -1; }

    __shared__ float4 tile[128];

    for (int t0 = 0; t0 < PP; t0 += 128) {
        const int j = t0 + threadIdx.x;
        const float x = pb[j * 3 + 0];
        const float y = pb[j * 3 + 1];
        const float z = pb[j * 3 + 2];
        tile[threadIdx.x] = make_float4(x, y, z, x * x + y * y + z * z);
        __syncthreads();

#pragma unroll 4
        for (int jj = 0; jj < 128; ++jj) {
            const float4 c = tile[jj];
            const float dot = qx * c.x + qy * c.y + qz * c.z;
            const float d2  = (qsq + c.w) - 2.0f * dot;
            if (d2 < kd[KK - 1]) {
                kd[KK - 1] = d2;
                ki[KK - 1] = t0 + jj;
#pragma unroll
                for (int s = KK - 1; s > 0; --s) {
                    if (kd[s] < kd[s - 1]) {
                        const float td = kd[s]; kd[s] = kd[s - 1]; kd[s - 1] = td;
                        const int   ti = ki[s]; ki[s] = ki[s - 1]; ki[s - 1] = ti;
                    }
                }
            }
        }
        __syncthreads();
    }

    const int base = (b * PP + q) * KK;
#pragma unroll
    for (int s = 0; s < KK; ++s) g_nbr[base + s] = ki[s];
}

// ---------------------------------------------------------------------------
// Weight prep: build mma B fragments (col-major [n,k]) from W[c][d], bf16 split.
// b0 = {Wt[n][k0], Wt[n][k0+1]}, b1 = {Wt[n][k0+8], Wt[n][k0+9]},
// n = nt*8 + lane/4, k0 = kc*16 + 2*(lane%4).  grid (16,8,2), block 32.
// ---------------------------------------------------------------------------
__global__ void wprep_kernel(const float* __restrict__ W1b,
                             const float* __restrict__ W2b) {
    const int nt = blockIdx.x, kc = blockIdx.y, L = blockIdx.z;
    const int l  = threadIdx.x;
    const float* W = L ? W2b : W1b;
    const int n  = nt * 8 + (l >> 2);
    const int k0 = kc * 16 + (l & 3) * 2;

    float v[4];
    v[0] = W[(k0 + 0) * NH + n];
    v[1] = W[(k0 + 1) * NH + n];
    v[2] = W[(k0 + 8) * NH + n];
    v[3] = W[(k0 + 9) * NH + n];
    float hi[4], lo[4];
#pragma unroll
    for (int i = 0; i < 4; ++i) {
        hi[i] = __bfloat162float(__float2bfloat16(v[i]));
        lo[i] = v[i] - hi[i];
    }
    const int idx = (nt * 8 + kc) * 32 + l;
    g_wfh[L][idx] = make_uint2(pack_bf2(hi[0], hi[1]), pack_bf2(hi[2], hi[3]));
    g_wfl[L][idx] = make_uint2(pack_bf2(lo[0], lo[1]), pack_bf2(lo[2], lo[3]));
}

// ---------------------------------------------------------------------------
// Edge-conv layer via mma.sync bf16 (3-term split). CTA = 8 points = 128 edges,
// 128 threads. A = activations (smem, hi+lo swizzled tiles), B = weights (regs,
// from fragment-order gmem). D[edges, dims]; max over 16 edges per point.
// ---------------------------------------------------------------------------
template <int MODE>
__global__ __launch_bounds__(128) void layer_mma(
    const float* __restrict__ pos,
    const float* __restrict__ Wsmall,   // MODE1: W1a[6,128]; MODE2: W2a rows 128..130
    const float* __restrict__ bh,       // MODE1: b1a
    const float* __restrict__ bo)       // out bias
{
    extern __shared__ char dsm[];
    __shared__ float sws[7 * NH];

    const int tid = threadIdx.x;
    const int wid = tid >> 5, lid = tid & 31;
    const int p0  = blockIdx.x * 8;
    const int L   = MODE - 1;

    char* actH = (char*)(((uintptr_t)dsm + 1023) & ~(uintptr_t)1023);
    char* actL = actH + 32768;

    // small weights (+bias) to smem
    if (MODE == 1) {
        for (int i = tid; i < 6 * NH; i += 128) sws[i] = Wsmall[i];
        sws[6 * NH + tid] = bh[tid];
    } else {
        for (int i = tid; i < 3 * NH; i += 128) sws[i] = Wsmall[i];
    }
    __syncthreads();

    // ---- Stage A: thread = edge (pt = tid>>4, k = tid&15) ------------------
    {
        const int p  = p0 + (tid >> 4);
        const int b  = p / PP;
        const int jg = b * PP + g_nbr[p * KK + (tid & 15)];
        const float pjx = pos[jg * 3 + 0], pjy = pos[jg * 3 + 1], pjz = pos[jg * 3 + 2];
        const float pix = pos[p * 3 + 0],  piy = pos[p * 3 + 1],  piz = pos[p * 3 + 2];
        float m[6];
        if (MODE == 1) {
            m[0] = pjx; m[1] = pjy; m[2] = pjz;
            m[3] = pjx - pix; m[4] = pjy - piy; m[5] = pjz - piz;
        } else {
            m[0] = pjx - pix; m[1] = pjy - piy; m[2] = pjz - piz;
        }
        const int r = tid;
        const uint32_t rowbase = r * 256;
        const int rx = (r & 7);
        const float* trow = g_t + (size_t)jg * NH;

#pragma unroll 4
        for (int d = 0; d < NH; d += 2) {
            float h0, h1;
            if (MODE == 1) {
                h0 = sws[6 * NH + d]; h1 = sws[6 * NH + d + 1];
#pragma unroll
                for (int u = 0; u < 6; ++u) {
                    h0 = fmaf(m[u], sws[u * NH + d], h0);
                    h1 = fmaf(m[u], sws[u * NH + d + 1], h1);
                }
            } else {
                const float2 t2 = *(const float2*)&trow[d];
                h0 = t2.x; h1 = t2.y;
#pragma unroll
                for (int u = 0; u < 3; ++u) {
                    h0 = fmaf(m[u], sws[u * NH + d], h0);
                    h1 = fmaf(m[u], sws[u * NH + d + 1], h1);
                }
            }
            h0 = fmaxf(h0, 0.f); h1 = fmaxf(h1, 0.f);
            const float h0h = __bfloat162float(__float2bfloat16(h0));
            const float h1h = __bfloat162float(__float2bfloat16(h1));
            const uint32_t off = rowbase + ((((d >> 3) ^ rx)) << 4) + ((d * 2) & 15);
            *(uint32_t*)(actH + off) = pack_bf2(h0h, h1h);
            *(uint32_t*)(actL + off) = pack_bf2(h0 - h0h, h1 - h1h);
        }
    }
    __syncthreads();

    // ---- GEMM + max epilogue ----------------------------------------------
    float* dst = (MODE == 1) ? g_h1 : g_h2;
    const uint32_t aHs = smem_u32(actH);
    const uint32_t aLs = smem_u32(actL);
    const int rowl = (lid & 15);
    const int koffl = ((lid >> 4) & 1) * 16;

#pragma unroll
    for (int g = 0; g < 2; ++g) {
        const int nt0 = wid * 4 + g * 2;

        // load this group's B fragments (weights) into registers
        uint2 bH[2][8], bL[2][8];
#pragma unroll
        for (int t = 0; t < 2; ++t)
#pragma unroll
            for (int kc = 0; kc < 8; ++kc) {
                const int idx = ((nt0 + t) * 8 + kc) * 32 + lid;
                bH[t][kc] = g_wfh[L][idx];
                bL[t][kc] = g_wfl[L][idx];
            }

        for (int mt = 0; mt < 8; ++mt) {
            const int r = mt * 16 + rowl;
            const uint32_t rbase = (uint32_t)r * 256;
            const int rx = (r & 7);
            float acc0[4] = {0.f, 0.f, 0.f, 0.f};
            float acc1[4] = {0.f, 0.f, 0.f, 0.f};

#pragma unroll
            for (int kc = 0; kc < 8; ++kc) {
                const int kb = kc * 32 + koffl;
                const uint32_t off = rbase + ((((kb >> 4) ^ rx)) << 4);
                uint32_t ah[4], al[4];
                ldsm_x4(ah, aHs + off);
                ldsm_x4(al, aLs + off);
                mma_bf16(acc0, ah, bH[0][kc]);
                mma_bf16(acc1, ah, bH[1][kc]);
                mma_bf16(acc0, ah, bL[0][kc]);
                mma_bf16(acc1, ah, bL[1][kc]);
                mma_bf16(acc0, al, bH[0][kc]);
                mma_bf16(acc1, al, bH[1][kc]);
            }

            // max over 16 edge rows (point p0+mt), bias, relu, store
            const int p = p0 + mt;
#pragma unroll
            for (int t = 0; t < 2; ++t) {
                float* a = t ? acc1 : acc0;
                float c0 = fmaxf(a[0], a[2]);
                float c1 = fmaxf(a[1], a[3]);
#pragma unroll
                for (int s = 4; s <= 16; s <<= 1) {
                    c0 = fmaxf(c0, __shfl_xor_sync(0xffffffffu, c0, s));
                    c1 = fmaxf(c1, __shfl_xor_sync(0xffffffffu, c1, s));
                }
                if (lid < 4) {
                    const int n0 = (nt0 + t) * 8 + 2 * lid;
                    const float2 bv = *(const float2*)&bo[n0];
                    float2 o;
                    o.x = fmaxf(c0 + bv.x, 0.f);
                    o.y = fmaxf(c1 + bv.y, 0.f);
                    *(float2*)&dst[(size_t)p * NH + n0] = o;
                }
            }
        }
    }
}

// ---------------------------------------------------------------------------
// t-precompute: g_t[r] = g_h1[r] @ W2a[0:128] + b2a (fp32, f32x2 packed).
// ---------------------------------------------------------------------------
__global__ __launch_bounds__(128) void tprep_kernel(
    const float* __restrict__ Wb, const float* __restrict__ bo)
{
    __shared__ __align__(16) float hid[16][NH];
    const int tid = threadIdx.x;
    const int wid = tid >> 5, lid = tid & 31;
    const int row0 = blockIdx.x * 16;

#pragma unroll
    for (int r = 0; r < 16; ++r)
        hid[r][tid] = g_h1[(size_t)(row0 + r) * NH + tid];
    __syncthreads();

    const int rb = wid * 4;
    const int d0 = lid * 4;

    u64 acc[4][2];
#pragma unroll
    for (int r = 0; r < 4; ++r) { acc[r][0] = 0ULL; acc[r][1] = 0ULL; }

#pragma unroll 2
    for (int c = 0; c < NH; c += 4) {
        const ulonglong2 wa  = *(const ulonglong2*)&Wb[(c + 0) * NH + d0];
        const ulonglong2 wb2 = *(const ulonglong2*)&Wb[(c + 1) * NH + d0];
        const ulonglong2 wc2 = *(const ulonglong2*)&Wb[(c + 2) * NH + d0];
        const ulonglong2 wd2 = *(const ulonglong2*)&Wb[(c + 3) * NH + d0];
#pragma unroll
        for (int r = 0; r < 4; ++r) {
            const float4 h4 = *(const float4*)&hid[rb + r][c];
            const u64 h0 = pack_dup(h4.x);
            const u64 h1 = pack_dup(h4.y);
            const u64 h2 = pack_dup(h4.z);
            const u64 h3 = pack_dup(h4.w);
            acc[r][0] = ffma2(h0, wa.x,  acc[r][0]);
            acc[r][1] = ffma2(h0, wa.y,  acc[r][1]);
            acc[r][0] = ffma2(h1, wb2.x, acc[r][0]);
            acc[r][1] = ffma2(h1, wb2.y, acc[r][1]);
            acc[r][0] = ffma2(h2, wc2.x, acc[r][0]);
            acc[r][1] = ffma2(h2, wc2.y, acc[r][1]);
            acc[r][0] = ffma2(h3, wd2.x, acc[r][0]);
            acc[r][1] = ffma2(h3, wd2.y, acc[r][1]);
        }
    }

    const float4 bv = *(const float4*)&bo[d0];
#pragma unroll
    for (int r = 0; r < 4; ++r) {
        const float2 f0 = unpack2(acc[r][0]);
        const float2 f1 = unpack2(acc[r][1]);
        float4 o;
        o.x = f0.x + bv.x; o.y = f0.y + bv.y;
        o.z = f1.x + bv.z; o.w = f1.y + bv.w;
        *(float4*)&g_t[(size_t)(row0 + rb + r) * NH + d0] = o;
    }
}

// ---------------------------------------------------------------------------
// Global max pool + classifier
// ---------------------------------------------------------------------------
__global__ void pool_kernel(const float* __restrict__ Wc,
                            const float* __restrict__ bc,
                            float* __restrict__ out) {
    const int b   = blockIdx.x;
    const int tid = threadIdx.x;
    const float* hb = g_h2 + (size_t)b * PP * NH;

    float m0 = -3.4e38f, m1 = m0, m2 = m0, m3 = m0;
    for (int p = 0; p < PP; p += 4) {
        m0 = fmaxf(m0, hb[(size_t)(p + 0) * NH + tid]);
        m1 = fmaxf(m1, hb[(size_t)(p + 1) * NH + tid]);
        m2 = fmaxf(m2, hb[(size_t)(p + 2) * NH + tid]);
        m3 = fmaxf(m3, hb[(size_t)(p + 3) * NH + tid]);
    }
    __shared__ float sg[NH];
    sg[tid] = fmaxf(fmaxf(m0, m1), fmaxf(m2, m3));
    __syncthreads();

    if (tid < 10) {
        float a = bc[tid];
#pragma unroll 8
        for (int d = 0; d < NH; ++d) a = fmaf(sg[d], Wc[d * 10 + tid], a);
        out[b * 10 + tid] = a;
    }
}

// ---------------------------------------------------------------------------
extern "C" void kernel_launch(void* const* d_in, const int* in_sizes, int n_in,
                              void* d_out, int out_size) {
    const float* pos = (const float*)d_in[0];
    const float* W1a = (const float*)d_in[2];
    const float* b1a = (const float*)d_in[3];
    const float* W1b = (const float*)d_in[4];
    const float* b1b = (const float*)d_in[5];
    const float* W2a = (const float*)d_in[6];
    const float* b2a = (const float*)d_in[7];
    const float* W2b = (const float*)d_in[8];
    const float* b2b = (const float*)d_in[9];
    const float* Wc  = (const float*)d_in[10];
    const float* bc  = (const float*)d_in[11];
    float* out = (float*)d_out;

    const int DSM = 65536 + 1024;   // act hi+lo tiles + alignment pad
    cudaFuncSetAttribute(layer_mma<1>, cudaFuncAttributeMaxDynamicSharedMemorySize, DSM);
    cudaFuncSetAttribute(layer_mma<2>, cudaFuncAttributeMaxDynamicSharedMemorySize, DSM);

    knn_kernel<<<dim3(PP / 128, BB), 128>>>(pos);
    wprep_kernel<<<dim3(16, 8, 2), 32>>>(W1b, W2b);
    layer_mma<1><<<BB * PP / 8, 128, DSM>>>(pos, W1a, b1a, b1b);
    tprep_kernel<<<BB * PP / 16, 128>>>(W2a, b2a);
    layer_mma<2><<<BB * PP / 8, 128, DSM>>>(pos, W2a + 128 * NH, nullptr, b2b);
    pool_kernel<<<BB, 128>>>(Wc, bc, out);
}

// round 7
// speedup vs baseline: 2.4252x; 1.4106x over previous
#include <cuda_runtime.h>
#include <cuda_bf16.h>
#include <math.h>
#include <stdint.h>

#define BB 32
#define PP 2048
#define KK 16
#define NH 128

typedef unsigned long long u64;

// Scratch (no allocations allowed).
__device__ int   g_nbr[BB * PP * KK];
__device__ float g_h1[BB * PP * NH];
__device__ float g_t [BB * PP * NH];
__device__ float g_h2[BB * PP * NH];
// Weight B-fragments in mma register order: [layer][(nt*8+kc)*32+lane] -> uint2{b0,b1}
__device__ uint2 g_wfh[2][16 * 8 * 32];
__device__ uint2 g_wfl[2][16 * 8 * 32];

// ---- helpers ---------------------------------------------------------------
__device__ __forceinline__ uint32_t smem_u32(const void* p) {
    return (uint32_t)__cvta_generic_to_shared(p);
}
__device__ __forceinline__ u64 pack_dup(float v) {
    u64 r; asm("mov.b64 %0, {%1, %1};" : "=l"(r) : "f"(v)); return r;
}
__device__ __forceinline__ u64 ffma2(u64 a, u64 b, u64 c) {
    u64 d; asm("fma.rn.f32x2 %0, %1, %2, %3;" : "=l"(d) : "l"(a), "l"(b), "l"(c));
    return d;
}
__device__ __forceinline__ float2 unpack2(u64 v) {
    float2 f; asm("mov.b64 {%0, %1}, %2;" : "=f"(f.x), "=f"(f.y) : "l"(v));
    return f;
}
__device__ __forceinline__ uint32_t pack_bf2(float a, float b) {
    return (uint32_t)__bfloat16_as_ushort(__float2bfloat16(a)) |
           ((uint32_t)__bfloat16_as_ushort(__float2bfloat16(b)) << 16);
}

__device__ __forceinline__ void ldsm_x4(uint32_t* r, uint32_t addr) {
    asm volatile("ldmatrix.sync.aligned.m8n8.x4.shared.b16 {%0,%1,%2,%3}, [%4];"
                 : "=r"(r[0]), "=r"(r[1]), "=r"(r[2]), "=r"(r[3]) : "r"(addr));
}
__device__ __forceinline__ void mma_bf16(float* d, const uint32_t* a, uint2 b) {
    asm volatile(
        "mma.sync.aligned.m16n8k16.row.col.f32.bf16.bf16.f32 "
        "{%0,%1,%2,%3}, {%4,%5,%6,%7}, {%8,%9}, {%0,%1,%2,%3};"
        : "+f"(d[0]), "+f"(d[1]), "+f"(d[2]), "+f"(d[3])
        : "r"(a[0]), "r"(a[1]), "r"(a[2]), "r"(a[3]), "r"(b.x), "r"(b.y));
}

// ---------------------------------------------------------------------------
// KNN (unchanged, known-correct)
// ---------------------------------------------------------------------------
__global__ void knn_kernel(const float* __restrict__ pos) {
    const int b = blockIdx.y;
    const int q = blockIdx.x * blockDim.x + threadIdx.x;
    const float* pb = pos + (size_t)b * PP * 3;

    const float qx = pb[q * 3 + 0];
    const float qy = pb[q * 3 + 1];
    const float qz = pb[q * 3 + 2];
    const float qsq = qx * qx + qy * qy + qz * qz;

    float kd[KK];
    int   ki[KK];
#pragma unroll
    for (int s = 0; s < KK; ++s) { kd[s] = 3.4e38f; ki[s] = -1; }

    __shared__ float4 tile[128];

    for (int t0 = 0; t0 < PP; t0 += 128) {
        const int j = t0 + threadIdx.x;
        const float x = pb[j * 3 + 0];
        const float y = pb[j * 3 + 1];
        const float z = pb[j * 3 + 2];
        tile[threadIdx.x] = make_float4(x, y, z, x * x + y * y + z * z);
        __syncthreads();

#pragma unroll 4
        for (int jj = 0; jj < 128; ++jj) {
            const float4 c = tile[jj];
            const float dot = qx * c.x + qy * c.y + qz * c.z;
            const float d2  = (qsq + c.w) - 2.0f * dot;
            if (d2 < kd[KK - 1]) {
                kd[KK - 1] = d2;
                ki[KK - 1] = t0 + jj;
#pragma unroll
                for (int s = KK - 1; s > 0; --s) {
                    if (kd[s] < kd[s - 1]) {
                        const float td = kd[s]; kd[s] = kd[s - 1]; kd[s - 1] = td;
                        const int   ti = ki[s]; ki[s] = ki[s - 1]; ki[s - 1] = ti;
                    }
                }
            }
        }
        __syncthreads();
    }

    const int base = (b * PP + q) * KK;
#pragma unroll
    for (int s = 0; s < KK; ++s) g_nbr[base + s] = ki[s];
}

// ---------------------------------------------------------------------------
// Weight prep: build mma B fragments (col-major [n,k]) from W[c][d], bf16 split.
// ---------------------------------------------------------------------------
__global__ void wprep_kernel(const float* __restrict__ W1b,
                             const float* __restrict__ W2b) {
    const int nt = blockIdx.x, kc = blockIdx.y, L = blockIdx.z;
    const int l  = threadIdx.x;
    const float* W = L ? W2b : W1b;
    const int n  = nt * 8 + (l >> 2);
    const int k0 = kc * 16 + (l & 3) * 2;

    float v[4];
    v[0] = W[(k0 + 0) * NH + n];
    v[1] = W[(k0 + 1) * NH + n];
    v[2] = W[(k0 + 8) * NH + n];
    v[3] = W[(k0 + 9) * NH + n];
    float hi[4], lo[4];
#pragma unroll
    for (int i = 0; i < 4; ++i) {
        hi[i] = __bfloat162float(__float2bfloat16(v[i]));
        lo[i] = v[i] - hi[i];
    }
    const int idx = (nt * 8 + kc) * 32 + l;
    g_wfh[L][idx] = make_uint2(pack_bf2(hi[0], hi[1]), pack_bf2(hi[2], hi[3]));
    g_wfl[L][idx] = make_uint2(pack_bf2(lo[0], lo[1]), pack_bf2(lo[2], lo[3]));
}

// ---------------------------------------------------------------------------
// Edge-conv layer via mma.sync bf16 (3-term split). CTA = 8 points = 128 edges.
// Stage A: warp-cooperative (coalesced t_j row loads, lane owns 4 dims).
// GEMM: kc-outer / mt-inner for ILP; D[edges, dims]; max over 16 edges/point.
// ---------------------------------------------------------------------------
template <int MODE>
__global__ __launch_bounds__(128) void layer_mma(
    const float* __restrict__ pos,
    const float* __restrict__ Wsmall,   // MODE1: W1a[6,128]; MODE2: W2a rows 128..130
    const float* __restrict__ bh,       // MODE1: b1a
    const float* __restrict__ bo)       // out bias
{
    extern __shared__ char dsm[];
    __shared__ float sM[8][KK][6];
    __shared__ int   sJ[8][KK];

    const int tid = threadIdx.x;
    const int wid = tid >> 5, lid = tid & 31;
    const int p0  = blockIdx.x * 8;
    const int L   = MODE - 1;

    char* actH = (char*)(((uintptr_t)dsm + 1023) & ~(uintptr_t)1023);
    char* actL = actH + 32768;

    // ---- neighbor / message prep: thread -> (pt = tid>>4, k = tid&15) ------
    {
        const int pt = tid >> 4, k = tid & 15;
        const int p  = p0 + pt;
        const int b  = p / PP;
        const int jg = b * PP + g_nbr[p * KK + k];
        sJ[pt][k] = jg;
        const float pjx = pos[jg * 3 + 0], pjy = pos[jg * 3 + 1], pjz = pos[jg * 3 + 2];
        const float pix = pos[p * 3 + 0],  piy = pos[p * 3 + 1],  piz = pos[p * 3 + 2];
        if (MODE == 1) {
            sM[pt][k][0] = pjx; sM[pt][k][1] = pjy; sM[pt][k][2] = pjz;
            sM[pt][k][3] = pjx - pix; sM[pt][k][4] = pjy - piy; sM[pt][k][5] = pjz - piz;
        } else {
            sM[pt][k][0] = pjx - pix; sM[pt][k][1] = pjy - piy; sM[pt][k][2] = pjz - piz;
        }
    }
    __syncthreads();

    // ---- Stage A: warp w builds edges 32w..32w+31; lane owns dims 4l..4l+3 -
    {
        const int d0 = lid * 4;
        float4 wsm4[6];
        const int NSM = (MODE == 1) ? 6 : 3;
#pragma unroll
        for (int u = 0; u < 6; ++u)
            wsm4[u] = (u < NSM) ? *(const float4*)&Wsmall[u * NH + d0]
                                : make_float4(0.f, 0.f, 0.f, 0.f);
        float4 bh4 = make_float4(0.f, 0.f, 0.f, 0.f);
        if (MODE == 1) bh4 = *(const float4*)&bh[d0];

        const uint32_t lane_off = (((uint32_t)(lid >> 1)) << 4) + ((lid & 1) << 3);

#pragma unroll 4
        for (int i = 0; i < 32; ++i) {
            const int e  = wid * 32 + i;
            const int pt = e >> 4, k = e & 15;
            float h0, h1, h2, h3;
            if (MODE == 1) {
                h0 = bh4.x; h1 = bh4.y; h2 = bh4.z; h3 = bh4.w;
#pragma unroll
                for (int u = 0; u < 6; ++u) {
                    const float mu = sM[pt][k][u];
                    h0 = fmaf(mu, wsm4[u].x, h0);
                    h1 = fmaf(mu, wsm4[u].y, h1);
                    h2 = fmaf(mu, wsm4[u].z, h2);
                    h3 = fmaf(mu, wsm4[u].w, h3);
                }
            } else {
                const float4 t4 = *(const float4*)&g_t[(size_t)sJ[pt][k] * NH + d0];
                h0 = t4.x; h1 = t4.y; h2 = t4.z; h3 = t4.w;
#pragma unroll
                for (int u = 0; u < 3; ++u) {
                    const float mu = sM[pt][k][u];
                    h0 = fmaf(mu, wsm4[u].x, h0);
                    h1 = fmaf(mu, wsm4[u].y, h1);
                    h2 = fmaf(mu, wsm4[u].z, h2);
                    h3 = fmaf(mu, wsm4[u].w, h3);
                }
            }
            h0 = fmaxf(h0, 0.f); h1 = fmaxf(h1, 0.f);
            h2 = fmaxf(h2, 0.f); h3 = fmaxf(h3, 0.f);
            const float h0h = __bfloat162float(__float2bfloat16(h0));
            const float h1h = __bfloat162float(__float2bfloat16(h1));
            const float h2h = __bfloat162float(__float2bfloat16(h2));
            const float h3h = __bfloat162float(__float2bfloat16(h3));

            // row e layout: byte(d) = e*256 + (((d>>3)^(e&7))<<4) + ((d*2)&15)
            const uint32_t off = (uint32_t)e * 256 +
                                 (lane_off ^ (((uint32_t)(e & 7)) << 4));
            *(uint2*)(actH + off) =
                make_uint2(pack_bf2(h0h, h1h), pack_bf2(h2h, h3h));
            *(uint2*)(actL + off) =
                make_uint2(pack_bf2(h0 - h0h, h1 - h1h), pack_bf2(h2 - h2h, h3 - h3h));
        }
    }
    __syncthreads();

    // ---- GEMM (kc outer, mt inner) + max epilogue --------------------------
    float* dst = (MODE == 1) ? g_h1 : g_h2;
    const uint32_t aHs = smem_u32(actH);
    const uint32_t aLs = smem_u32(actL);
    const int rowl  = (lid & 15);
    const int koffl = ((lid >> 4) & 1) * 16;

#pragma unroll
    for (int g = 0; g < 2; ++g) {
        const int nt0 = wid * 4 + g * 2;

        float acc[8][2][4];
#pragma unroll
        for (int mt = 0; mt < 8; ++mt)
#pragma unroll
            for (int t = 0; t < 2; ++t)
#pragma unroll
                for (int c = 0; c < 4; ++c) acc[mt][t][c] = 0.f;

#pragma unroll
        for (int kc = 0; kc < 8; ++kc) {
            const uint2 bH0 = g_wfh[L][((nt0 + 0) * 8 + kc) * 32 + lid];
            const uint2 bH1 = g_wfh[L][((nt0 + 1) * 8 + kc) * 32 + lid];
            const uint2 bL0 = g_wfl[L][((nt0 + 0) * 8 + kc) * 32 + lid];
            const uint2 bL1 = g_wfl[L][((nt0 + 1) * 8 + kc) * 32 + lid];
            const int kx = kc * 2 + (koffl >> 4);

#pragma unroll
            for (int mt = 0; mt < 8; ++mt) {
                const int r = mt * 16 + rowl;
                const uint32_t off = ((uint32_t)r << 8) +
                                     ((uint32_t)(kx ^ (r & 7)) << 4);
                uint32_t ah[4], al[4];
                ldsm_x4(ah, aHs + off);
                ldsm_x4(al, aLs + off);
                mma_bf16(acc[mt][0], ah, bH0);
                mma_bf16(acc[mt][1], ah, bH1);
                mma_bf16(acc[mt][0], ah, bL0);
                mma_bf16(acc[mt][1], ah, bL1);
                mma_bf16(acc[mt][0], al, bH0);
                mma_bf16(acc[mt][1], al, bH1);
            }
        }

        // epilogue: max over 16 edge rows per point, bias, relu, store
#pragma unroll
        for (int mt = 0; mt < 8; ++mt) {
            const int p = p0 + mt;
#pragma unroll
            for (int t = 0; t < 2; ++t) {
                float c0 = fmaxf(acc[mt][t][0], acc[mt][t][2]);
                float c1 = fmaxf(acc[mt][t][1], acc[mt][t][3]);
#pragma unroll
                for (int s = 4; s <= 16; s <<= 1) {
                    c0 = fmaxf(c0, __shfl_xor_sync(0xffffffffu, c0, s));
                    c1 = fmaxf(c1, __shfl_xor_sync(0xffffffffu, c1, s));
                }
                if (lid < 4) {
                    const int n0 = (nt0 + t) * 8 + 2 * lid;
                    const float2 bv = *(const float2*)&bo[n0];
                    float2 o;
                    o.x = fmaxf(c0 + bv.x, 0.f);
                    o.y = fmaxf(c1 + bv.y, 0.f);
                    *(float2*)&dst[(size_t)p * NH + n0] = o;
                }
            }
        }
    }
}

// ---------------------------------------------------------------------------
// t-precompute: g_t[r] = g_h1[r] @ W2a[0:128] + b2a (fp32, f32x2 packed).
// ---------------------------------------------------------------------------
__global__ __launch_bounds__(128) void tprep_kernel(
    const float* __restrict__ Wb, const float* __restrict__ bo)
{
    __shared__ __align__(16) float hid[16][NH];
    const int tid = threadIdx.x;
    const int wid = tid >> 5, lid = tid & 31;
    const int row0 = blockIdx.x * 16;

#pragma unroll
    for (int r = 0; r < 16; ++r)
        hid[r][tid] = g_h1[(size_t)(row0 + r) * NH + tid];
    __syncthreads();

    const int rb = wid * 4;
    const int d0 = lid * 4;

    u64 acc[4][2];
#pragma unroll
    for (int r = 0; r < 4; ++r) { acc[r][0] = 0ULL; acc[r][1] = 0ULL; }

#pragma unroll 2
    for (int c = 0; c < NH; c += 4) {
        const ulonglong2 wa  = *(const ulonglong2*)&Wb[(c + 0) * NH + d0];
        const ulonglong2 wb2 = *(const ulonglong2*)&Wb[(c + 1) * NH + d0];
        const ulonglong2 wc2 = *(const ulonglong2*)&Wb[(c + 2) * NH + d0];
        const ulonglong2 wd2 = *(const ulonglong2*)&Wb[(c + 3) * NH + d0];
#pragma unroll
        for (int r = 0; r < 4; ++r) {
            const float4 h4 = *(const float4*)&hid[rb + r][c];
            const u64 h0 = pack_dup(h4.x);
            const u64 h1 = pack_dup(h4.y);
            const u64 h2 = pack_dup(h4.z);
            const u64 h3 = pack_dup(h4.w);
            acc[r][0] = ffma2(h0, wa.x,  acc[r][0]);
            acc[r][1] = ffma2(h0, wa.y,  acc[r][1]);
            acc[r][0] = ffma2(h1, wb2.x, acc[r][0]);
            acc[r][1] = ffma2(h1, wb2.y, acc[r][1]);
            acc[r][0] = ffma2(h2, wc2.x, acc[r][0]);
            acc[r][1] = ffma2(h2, wc2.y, acc[r][1]);
            acc[r][0] = ffma2(h3, wd2.x, acc[r][0]);
            acc[r][1] = ffma2(h3, wd2.y, acc[r][1]);
        }
    }

    const float4 bv = *(const float4*)&bo[d0];
#pragma unroll
    for (int r = 0; r < 4; ++r) {
        const float2 f0 = unpack2(acc[r][0]);
        const float2 f1 = unpack2(acc[r][1]);
        float4 o;
        o.x = f0.x + bv.x; o.y = f0.y + bv.y;
        o.z = f1.x + bv.z; o.w = f1.y + bv.w;
        *(float4*)&g_t[(size_t)(row0 + rb + r) * NH + d0] = o;
    }
}

// ---------------------------------------------------------------------------
// Global max pool + classifier
// ---------------------------------------------------------------------------
__global__ void pool_kernel(const float* __restrict__ Wc,
                            const float* __restrict__ bc,
                            float* __restrict__ out) {
    const int b   = blockIdx.x;
    const int tid = threadIdx.x;
    const float* hb = g_h2 + (size_t)b * PP * NH;

    float m0 = -3.4e38f, m1 = m0, m2 = m0, m3 = m0;
    for (int p = 0; p < PP; p += 4) {
        m0 = fmaxf(m0, hb[(size_t)(p + 0) * NH + tid]);
        m1 = fmaxf(m1, hb[(size_t)(p + 1) * NH + tid]);
        m2 = fmaxf(m2, hb[(size_t)(p + 2) * NH + tid]);
        m3 = fmaxf(m3, hb[(size_t)(p + 3) * NH + tid]);
    }
    __shared__ float sg[NH];
    sg[tid] = fmaxf(fmaxf(m0, m1), fmaxf(m2, m3));
    __syncthreads();

    if (tid < 10) {
        float a = bc[tid];
#pragma unroll 8
        for (int d = 0; d < NH; ++d) a = fmaf(sg[d], Wc[d * 10 + tid], a);
        out[b * 10 + tid] = a;
    }
}

// ---------------------------------------------------------------------------
extern "C" void kernel_launch(void* const* d_in, const int* in_sizes, int n_in,
                              void* d_out, int out_size) {
    const float* pos = (const float*)d_in[0];
    const float* W1a = (const float*)d_in[2];
    const float* b1a = (const float*)d_in[3];
    const float* W1b = (const float*)d_in[4];
    const float* b1b = (const float*)d_in[5];
    const float* W2a = (const float*)d_in[6];
    const float* b2a = (const float*)d_in[7];
    const float* W2b = (const float*)d_in[8];
    const float* b2b = (const float*)d_in[9];
    const float* Wc  = (const float*)d_in[10];
    const float* bc  = (const float*)d_in[11];
    float* out = (float*)d_out;

    const int DSM = 65536 + 1024;   // act hi+lo tiles + alignment pad
    cudaFuncSetAttribute(layer_mma<1>, cudaFuncAttributeMaxDynamicSharedMemorySize, DSM);
    cudaFuncSetAttribute(layer_mma<2>, cudaFuncAttributeMaxDynamicSharedMemorySize, DSM);

    knn_kernel<<<dim3(PP / 128, BB), 128>>>(pos);
    wprep_kernel<<<dim3(16, 8, 2), 32>>>(W1b, W2b);
    layer_mma<1><<<BB * PP / 8, 128, DSM>>>(pos, W1a, b1a, b1b);
    tprep_kernel<<<BB * PP / 16, 128>>>(W2a, b2a);
    layer_mma<2><<<BB * PP / 8, 128, DSM>>>(pos, W2a + 128 * NH, nullptr, b2b);
    pool_kernel<<<BB, 128>>>(Wc, bc, out);
}

// round 8
// speedup vs baseline: 2.8479x; 1.1743x over previous
#include <cuda_runtime.h>
#include <cuda_fp16.h>
#include <math.h>
#include <stdint.h>

#define BB 32
#define PP 2048
#define KK 16
#define NH 128

typedef unsigned long long u64;

// Scratch (no allocations allowed).
__device__ int   g_nbr[BB * PP * KK];
__device__ float g_h1[BB * PP * NH];
__device__ float g_t [BB * PP * NH];
__device__ float g_h2[BB * PP * NH];
// Weight B-fragments (fp16) in mma register order:
// [layer][(nt*8+kc)*32+lane] -> uint2{b0,b1}; hi = fp16(W), lo = fp16(W - hi)
__device__ uint2 g_wfh[2][16 * 8 * 32];
__device__ uint2 g_wfl[2][16 * 8 * 32];

// ---- helpers ---------------------------------------------------------------
__device__ __forceinline__ uint32_t smem_u32(const void* p) {
    return (uint32_t)__cvta_generic_to_shared(p);
}
__device__ __forceinline__ u64 pack_dup(float v) {
    u64 r; asm("mov.b64 %0, {%1, %1};" : "=l"(r) : "f"(v)); return r;
}
__device__ __forceinline__ u64 ffma2(u64 a, u64 b, u64 c) {
    u64 d; asm("fma.rn.f32x2 %0, %1, %2, %3;" : "=l"(d) : "l"(a), "l"(b), "l"(c));
    return d;
}
__device__ __forceinline__ float2 unpack2(u64 v) {
    float2 f; asm("mov.b64 {%0, %1}, %2;" : "=f"(f.x), "=f"(f.y) : "l"(v));
    return f;
}
__device__ __forceinline__ uint32_t pack_h2(float a, float b) {
    const __half2 h = __floats2half2_rn(a, b);
    return *(const uint32_t*)&h;
}

__device__ __forceinline__ void ldsm_x4(uint32_t* r, uint32_t addr) {
    asm volatile("ldmatrix.sync.aligned.m8n8.x4.shared.b16 {%0,%1,%2,%3}, [%4];"
                 : "=r"(r[0]), "=r"(r[1]), "=r"(r[2]), "=r"(r[3]) : "r"(addr));
}
__device__ __forceinline__ void mma_f16(float* d, const uint32_t* a, uint2 b) {
    asm volatile(
        "mma.sync.aligned.m16n8k16.row.col.f32.f16.f16.f32 "
        "{%0,%1,%2,%3}, {%4,%5,%6,%7}, {%8,%9}, {%0,%1,%2,%3};"
        : "+f"(d[0]), "+f"(d[1]), "+f"(d[2]), "+f"(d[3])
        : "r"(a[0]), "r"(a[1]), "r"(a[2]), "r"(a[3]), "r"(b.x), "r"(b.y));
}

// ---------------------------------------------------------------------------
// KNN (unchanged, known-correct)
// ---------------------------------------------------------------------------
__global__ void knn_kernel(const float* __restrict__ pos) {
    const int b = blockIdx.y;
    const int q = blockIdx.x * blockDim.x + threadIdx.x;
    const float* pb = pos + (size_t)b * PP * 3;

    const float qx = pb[q * 3 + 0];
    const float qy = pb[q * 3 + 1];
    const float qz = pb[q * 3 + 2];
    const float qsq = qx * qx + qy * qy + qz * qz;

    float kd[KK];
    int   ki[KK];
#pragma unroll
    for (int s = 0; s < KK; ++s) { kd[s] = 3.4e38f; ki[s] = -1; }

    __shared__ float4 tile[128];

    for (int t0 = 0; t0 < PP; t0 += 128) {
        const int j = t0 + threadIdx.x;
        const float x = pb[j * 3 + 0];
        const float y = pb[j * 3 + 1];
        const float z = pb[j * 3 + 2];
        tile[threadIdx.x] = make_float4(x, y, z, x * x + y * y + z * z);
        __syncthreads();

#pragma unroll 4
        for (int jj = 0; jj < 128; ++jj) {
            const float4 c = tile[jj];
            const float dot = qx * c.x + qy * c.y + qz * c.z;
            const float d2  = (qsq + c.w) - 2.0f * dot;
            if (d2 < kd[KK - 1]) {
                kd[KK - 1] = d2;
                ki[KK - 1] = t0 + jj;
#pragma unroll
                for (int s = KK - 1; s > 0; --s) {
                    if (kd[s] < kd[s - 1]) {
                        const float td = kd[s]; kd[s] = kd[s - 1]; kd[s - 1] = td;
                        const int   ti = ki[s]; ki[s] = ki[s - 1]; ki[s - 1] = ti;
                    }
                }
            }
        }
        __syncthreads();
    }

    const int base = (b * PP + q) * KK;
#pragma unroll
    for (int s = 0; s < KK; ++s) g_nbr[base + s] = ki[s];
}

// ---------------------------------------------------------------------------
// Weight prep: fp16 hi/lo split fragments (col-major [n,k]) from W[c][d].
// ---------------------------------------------------------------------------
__global__ void wprep_kernel(const float* __restrict__ W1b,
                             const float* __restrict__ W2b) {
    const int nt = blockIdx.x, kc = blockIdx.y, L = blockIdx.z;
    const int l  = threadIdx.x;
    const float* W = L ? W2b : W1b;
    const int n  = nt * 8 + (l >> 2);
    const int k0 = kc * 16 + (l & 3) * 2;

    float v[4];
    v[0] = W[(k0 + 0) * NH + n];
    v[1] = W[(k0 + 1) * NH + n];
    v[2] = W[(k0 + 8) * NH + n];
    v[3] = W[(k0 + 9) * NH + n];
    float hi[4], lo[4];
#pragma unroll
    for (int i = 0; i < 4; ++i) {
        hi[i] = __half2float(__float2half_rn(v[i]));
        lo[i] = v[i] - hi[i];
    }
    const int idx = (nt * 8 + kc) * 32 + l;
    g_wfh[L][idx] = make_uint2(pack_h2(hi[0], hi[1]), pack_h2(hi[2], hi[3]));
    g_wfl[L][idx] = make_uint2(pack_h2(lo[0], lo[1]), pack_h2(lo[2], lo[3]));
}

// ---------------------------------------------------------------------------
// Edge-conv layer via mma.sync fp16, 2-term weight split:
// D = Ah*(Bh + Bl), error ~ fp16 rounding of activations (~3e-4 rel).
// CTA = 8 points = 128 edges. A (acts) fp16 in one 32KB swizzled smem tile.
// ---------------------------------------------------------------------------
template <int MODE>
__global__ __launch_bounds__(128) void layer_mma(
    const float* __restrict__ pos,
    const float* __restrict__ Wsmall,   // MODE1: W1a[6,128]; MODE2: W2a rows 128..130
    const float* __restrict__ bh,       // MODE1: b1a
    const float* __restrict__ bo)       // out bias
{
    extern __shared__ char dsm[];
    __shared__ float sM[8][KK][6];
    __shared__ int   sJ[8][KK];

    const int tid = threadIdx.x;
    const int wid = tid >> 5, lid = tid & 31;
    const int p0  = blockIdx.x * 8;
    const int L   = MODE - 1;

    char* actH = (char*)(((uintptr_t)dsm + 1023) & ~(uintptr_t)1023);

    // ---- neighbor / message prep: thread -> (pt = tid>>4, k = tid&15) ------
    {
        const int pt = tid >> 4, k = tid & 15;
        const int p  = p0 + pt;
        const int b  = p / PP;
        const int jg = b * PP + g_nbr[p * KK + k];
        sJ[pt][k] = jg;
        const float pjx = pos[jg * 3 + 0], pjy = pos[jg * 3 + 1], pjz = pos[jg * 3 + 2];
        const float pix = pos[p * 3 + 0],  piy = pos[p * 3 + 1],  piz = pos[p * 3 + 2];
        if (MODE == 1) {
            sM[pt][k][0] = pjx; sM[pt][k][1] = pjy; sM[pt][k][2] = pjz;
            sM[pt][k][3] = pjx - pix; sM[pt][k][4] = pjy - piy; sM[pt][k][5] = pjz - piz;
        } else {
            sM[pt][k][0] = pjx - pix; sM[pt][k][1] = pjy - piy; sM[pt][k][2] = pjz - piz;
        }
    }
    __syncthreads();

    // ---- Stage A: warp w builds edges 32w..32w+31; lane owns dims 4l..4l+3 -
    {
        const int d0 = lid * 4;
        float4 wsm4[6];
        const int NSM = (MODE == 1) ? 6 : 3;
#pragma unroll
        for (int u = 0; u < 6; ++u)
            wsm4[u] = (u < NSM) ? *(const float4*)&Wsmall[u * NH + d0]
                                : make_float4(0.f, 0.f, 0.f, 0.f);
        float4 bh4 = make_float4(0.f, 0.f, 0.f, 0.f);
        if (MODE == 1) bh4 = *(const float4*)&bh[d0];

        const uint32_t lane_off = (((uint32_t)(lid >> 1)) << 4) + ((lid & 1) << 3);

#pragma unroll 4
        for (int i = 0; i < 32; ++i) {
            const int e  = wid * 32 + i;
            const int pt = e >> 4, k = e & 15;
            float h0, h1, h2, h3;
            if (MODE == 1) {
                h0 = bh4.x; h1 = bh4.y; h2 = bh4.z; h3 = bh4.w;
#pragma unroll
                for (int u = 0; u < 6; ++u) {
                    const float mu = sM[pt][k][u];
                    h0 = fmaf(mu, wsm4[u].x, h0);
                    h1 = fmaf(mu, wsm4[u].y, h1);
                    h2 = fmaf(mu, wsm4[u].z, h2);
                    h3 = fmaf(mu, wsm4[u].w, h3);
                }
            } else {
                const float4 t4 = *(const float4*)&g_t[(size_t)sJ[pt][k] * NH + d0];
                h0 = t4.x; h1 = t4.y; h2 = t4.z; h3 = t4.w;
#pragma unroll
                for (int u = 0; u < 3; ++u) {
                    const float mu = sM[pt][k][u];
                    h0 = fmaf(mu, wsm4[u].x, h0);
                    h1 = fmaf(mu, wsm4[u].y, h1);
                    h2 = fmaf(mu, wsm4[u].z, h2);
                    h3 = fmaf(mu, wsm4[u].w, h3);
                }
            }
            h0 = fmaxf(h0, 0.f); h1 = fmaxf(h1, 0.f);
            h2 = fmaxf(h2, 0.f); h3 = fmaxf(h3, 0.f);

            // row e layout: byte(d) = e*256 + (((d>>3)^(e&7))<<4) + ((d*2)&15)
            const uint32_t off = (uint32_t)e * 256 +
                                 (lane_off ^ (((uint32_t)(e & 7)) << 4));
            *(uint2*)(actH + off) = make_uint2(pack_h2(h0, h1), pack_h2(h2, h3));
        }
    }
    __syncthreads();

    // ---- GEMM (kc outer, mt inner) + max epilogue --------------------------
    float* dst = (MODE == 1) ? g_h1 : g_h2;
    const uint32_t aHs = smem_u32(actH);
    const int rowl  = (lid & 15);
    const int koffl = ((lid >> 4) & 1) * 16;

#pragma unroll
    for (int g = 0; g < 2; ++g) {
        const int nt0 = wid * 4 + g * 2;

        float acc[8][2][4];
#pragma unroll
        for (int mt = 0; mt < 8; ++mt)
#pragma unroll
            for (int t = 0; t < 2; ++t)
#pragma unroll
                for (int c = 0; c < 4; ++c) acc[mt][t][c] = 0.f;

#pragma unroll
        for (int kc = 0; kc < 8; ++kc) {
            const uint2 bH0 = g_wfh[L][((nt0 + 0) * 8 + kc) * 32 + lid];
            const uint2 bH1 = g_wfh[L][((nt0 + 1) * 8 + kc) * 32 + lid];
            const uint2 bL0 = g_wfl[L][((nt0 + 0) * 8 + kc) * 32 + lid];
            const uint2 bL1 = g_wfl[L][((nt0 + 1) * 8 + kc) * 32 + lid];
            const int kx = kc * 2 + (koffl >> 4);

#pragma unroll
            for (int mt = 0; mt < 8; ++mt) {
                const int r = mt * 16 + rowl;
                const uint32_t off = ((uint32_t)r << 8) +
                                     ((uint32_t)(kx ^ (r & 7)) << 4);
                uint32_t ah[4];
                ldsm_x4(ah, aHs + off);
                mma_f16(acc[mt][0], ah, bH0);
                mma_f16(acc[mt][1], ah, bH1);
                mma_f16(acc[mt][0], ah, bL0);
                mma_f16(acc[mt][1], ah, bL1);
            }
        }

        // epilogue: max over 16 edge rows per point, bias, relu, store
#pragma unroll
        for (int mt = 0; mt < 8; ++mt) {
            const int p = p0 + mt;
#pragma unroll
            for (int t = 0; t < 2; ++t) {
                float c0 = fmaxf(acc[mt][t][0], acc[mt][t][2]);
                float c1 = fmaxf(acc[mt][t][1], acc[mt][t][3]);
#pragma unroll
                for (int s = 4; s <= 16; s <<= 1) {
                    c0 = fmaxf(c0, __shfl_xor_sync(0xffffffffu, c0, s));
                    c1 = fmaxf(c1, __shfl_xor_sync(0xffffffffu, c1, s));
                }
                if (lid < 4) {
                    const int n0 = (nt0 + t) * 8 + 2 * lid;
                    const float2 bv = *(const float2*)&bo[n0];
                    float2 o;
                    o.x = fmaxf(c0 + bv.x, 0.f);
                    o.y = fmaxf(c1 + bv.y, 0.f);
                    *(float2*)&dst[(size_t)p * NH + n0] = o;
                }
            }
        }
    }
}

// ---------------------------------------------------------------------------
// t-precompute: g_t[r] = g_h1[r] @ W2a[0:128] + b2a (fp32, f32x2 packed).
// ---------------------------------------------------------------------------
__global__ __launch_bounds__(128) void tprep_kernel(
    const float* __restrict__ Wb, const float* __restrict__ bo)
{
    __shared__ __align__(16) float hid[16][NH];
    const int tid = threadIdx.x;
    const int wid = tid >> 5, lid = tid & 31;
    const int row0 = blockIdx.x * 16;

#pragma unroll
    for (int r = 0; r < 16; ++r)
        hid[r][tid] = g_h1[(size_t)(row0 + r) * NH + tid];
    __syncthreads();

    const int rb = wid * 4;
    const int d0 = lid * 4;

    u64 acc[4][2];
#pragma unroll
    for (int r = 0; r < 4; ++r) { acc[r][0] = 0ULL; acc[r][1] = 0ULL; }

#pragma unroll 2
    for (int c = 0; c < NH; c += 4) {
        const ulonglong2 wa  = *(const ulonglong2*)&Wb[(c + 0) * NH + d0];
        const ulonglong2 wb2 = *(const ulonglong2*)&Wb[(c + 1) * NH + d0];
        const ulonglong2 wc2 = *(const ulonglong2*)&Wb[(c + 2) * NH + d0];
        const ulonglong2 wd2 = *(const ulonglong2*)&Wb[(c + 3) * NH + d0];
#pragma unroll
        for (int r = 0; r < 4; ++r) {
            const float4 h4 = *(const float4*)&hid[rb + r][c];
            const u64 h0 = pack_dup(h4.x);
            const u64 h1 = pack_dup(h4.y);
            const u64 h2 = pack_dup(h4.z);
            const u64 h3 = pack_dup(h4.w);
            acc[r][0] = ffma2(h0, wa.x,  acc[r][0]);
            acc[r][1] = ffma2(h0, wa.y,  acc[r][1]);
            acc[r][0] = ffma2(h1, wb2.x, acc[r][0]);
            acc[r][1] = ffma2(h1, wb2.y, acc[r][1]);
            acc[r][0] = ffma2(h2, wc2.x, acc[r][0]);
            acc[r][1] = ffma2(h2, wc2.y, acc[r][1]);
            acc[r][0] = ffma2(h3, wd2.x, acc[r][0]);
            acc[r][1] = ffma2(h3, wd2.y, acc[r][1]);
        }
    }

    const float4 bv = *(const float4*)&bo[d0];
#pragma unroll
    for (int r = 0; r < 4; ++r) {
        const float2 f0 = unpack2(acc[r][0]);
        const float2 f1 = unpack2(acc[r][1]);
        float4 o;
        o.x = f0.x + bv.x; o.y = f0.y + bv.y;
        o.z = f1.x + bv.z; o.w = f1.y + bv.w;
        *(float4*)&g_t[(size_t)(row0 + rb + r) * NH + d0] = o;
    }
}

// ---------------------------------------------------------------------------
// Global max pool + classifier
// ---------------------------------------------------------------------------
__global__ void pool_kernel(const float* __restrict__ Wc,
                            const float* __restrict__ bc,
                            float* __restrict__ out) {
    const int b   = blockIdx.x;
    const int tid = threadIdx.x;
    const float* hb = g_h2 + (size_t)b * PP * NH;

    float m0 = -3.4e38f, m1 = m0, m2 = m0, m3 = m0;
    for (int p = 0; p < PP; p += 4) {
        m0 = fmaxf(m0, hb[(size_t)(p + 0) * NH + tid]);
        m1 = fmaxf(m1, hb[(size_t)(p + 1) * NH + tid]);
        m2 = fmaxf(m2, hb[(size_t)(p + 2) * NH + tid]);
        m3 = fmaxf(m3, hb[(size_t)(p + 3) * NH + tid]);
    }
    __shared__ float sg[NH];
    sg[tid] = fmaxf(fmaxf(m0, m1), fmaxf(m2, m3));
    __syncthreads();

    if (tid < 10) {
        float a = bc[tid];
#pragma unroll 8
        for (int d = 0; d < NH; ++d) a = fmaf(sg[d], Wc[d * 10 + tid], a);
        out[b * 10 + tid] = a;
    }
}

// ---------------------------------------------------------------------------
extern "C" void kernel_launch(void* const* d_in, const int* in_sizes, int n_in,
                              void* d_out, int out_size) {
    const float* pos = (const float*)d_in[0];
    const float* W1a = (const float*)d_in[2];
    const float* b1a = (const float*)d_in[3];
    const float* W1b = (const float*)d_in[4];
    const float* b1b = (const float*)d_in[5];
    const float* W2a = (const float*)d_in[6];
    const float* b2a = (const float*)d_in[7];
    const float* W2b = (const float*)d_in[8];
    const float* b2b = (const float*)d_in[9];
    const float* Wc  = (const float*)d_in[10];
    const float* bc  = (const float*)d_in[11];
    float* out = (float*)d_out;

    const int DSM = 32768 + 1024;   // single fp16 act tile + alignment pad
    cudaFuncSetAttribute(layer_mma<1>, cudaFuncAttributeMaxDynamicSharedMemorySize, DSM);
    cudaFuncSetAttribute(layer_mma<2>, cudaFuncAttributeMaxDynamicSharedMemorySize, DSM);

    knn_kernel<<<dim3(PP / 128, BB), 128>>>(pos);
    wprep_kernel<<<dim3(16, 8, 2), 32>>>(W1b, W2b);
    layer_mma<1><<<BB * PP / 8, 128, DSM>>>(pos, W1a, b1a, b1b);
    tprep_kernel<<<BB * PP / 16, 128>>>(W2a, b2a);
    layer_mma<2><<<BB * PP / 8, 128, DSM>>>(pos, W2a + 128 * NH, nullptr, b2b);
    pool_kernel<<<BB, 128>>>(Wc, bc, out);
}

// round 9
// speedup vs baseline: 3.1816x; 1.1172x over previous
#include <cuda_runtime.h>
#include <cuda_fp16.h>
#include <math.h>
#include <stdint.h>

#define BB 32
#define PP 2048
#define KK 16
#define NH 128

typedef unsigned long long u64;

// Scratch (no allocations allowed).
__device__ int   g_nbr[BB * PP * KK];
__device__ float g_h1[BB * PP * NH];
__device__ float g_t [BB * PP * NH];
__device__ float g_h2[BB * PP * NH];
// Weight B-fragments (fp16) in mma register order:
// [layer][(nt*8+kc)*32+lane] -> uint2{b0,b1}
__device__ uint2 g_wfh[2][16 * 8 * 32];

// ---- helpers ---------------------------------------------------------------
__device__ __forceinline__ uint32_t smem_u32(const void* p) {
    return (uint32_t)__cvta_generic_to_shared(p);
}
__device__ __forceinline__ u64 pack_dup(float v) {
    u64 r; asm("mov.b64 %0, {%1, %1};" : "=l"(r) : "f"(v)); return r;
}
__device__ __forceinline__ u64 ffma2(u64 a, u64 b, u64 c) {
    u64 d; asm("fma.rn.f32x2 %0, %1, %2, %3;" : "=l"(d) : "l"(a), "l"(b), "l"(c));
    return d;
}
__device__ __forceinline__ float2 unpack2(u64 v) {
    float2 f; asm("mov.b64 {%0, %1}, %2;" : "=f"(f.x), "=f"(f.y) : "l"(v));
    return f;
}
__device__ __forceinline__ uint32_t pack_h2(float a, float b) {
    const __half2 h = __floats2half2_rn(a, b);
    return *(const uint32_t*)&h;
}

__device__ __forceinline__ void ldsm_x4(uint32_t* r, uint32_t addr) {
    asm volatile("ldmatrix.sync.aligned.m8n8.x4.shared.b16 {%0,%1,%2,%3}, [%4];"
                 : "=r"(r[0]), "=r"(r[1]), "=r"(r[2]), "=r"(r[3]) : "r"(addr));
}
__device__ __forceinline__ void mma_f16(float* d, const uint32_t* a, uint2 b) {
    asm volatile(
        "mma.sync.aligned.m16n8k16.row.col.f32.f16.f16.f32 "
        "{%0,%1,%2,%3}, {%4,%5,%6,%7}, {%8,%9}, {%0,%1,%2,%3};"
        : "+f"(d[0]), "+f"(d[1]), "+f"(d[2]), "+f"(d[3])
        : "r"(a[0]), "r"(a[1]), "r"(a[2]), "r"(a[3]), "r"(b.x), "r"(b.y));
}

// ---------------------------------------------------------------------------
// KNN (unchanged, known-correct)
// ---------------------------------------------------------------------------
__global__ void knn_kernel(const float* __restrict__ pos) {
    const int b = blockIdx.y;
    const int q = blockIdx.x * blockDim.x + threadIdx.x;
    const float* pb = pos + (size_t)b * PP * 3;

    const float qx = pb[q * 3 + 0];
    const float qy = pb[q * 3 + 1];
    const float qz = pb[q * 3 + 2];
    const float qsq = qx * qx + qy * qy + qz * qz;

    float kd[KK];
    int   ki[KK];
#pragma unroll
    for (int s = 0; s < KK; ++s) { kd[s] = 3.4e38f; ki[s] = -1; }

    __shared__ float4 tile[128];

    for (int t0 = 0; t0 < PP; t0 += 128) {
        const int j = t0 + threadIdx.x;
        const float x = pb[j * 3 + 0];
        const float y = pb[j * 3 + 1];
        const float z = pb[j * 3 + 2];
        tile[threadIdx.x] = make_float4(x, y, z, x * x + y * y + z * z);
        __syncthreads();

#pragma unroll 4
        for (int jj = 0; jj < 128; ++jj) {
            const float4 c = tile[jj];
            const float dot = qx * c.x + qy * c.y + qz * c.z;
            const float d2  = (qsq + c.w) - 2.0f * dot;
            if (d2 < kd[KK - 1]) {
                kd[KK - 1] = d2;
                ki[KK - 1] = t0 + jj;
#pragma unroll
                for (int s = KK - 1; s > 0; --s) {
                    if (kd[s] < kd[s - 1]) {
                        const float td = kd[s]; kd[s] = kd[s - 1]; kd[s - 1] = td;
                        const int   ti = ki[s]; ki[s] = ki[s - 1]; ki[s - 1] = ti;
                    }
                }
            }
        }
        __syncthreads();
    }

    const int base = (b * PP + q) * KK;
#pragma unroll
    for (int s = 0; s < KK; ++s) g_nbr[base + s] = ki[s];
}

// ---------------------------------------------------------------------------
// Weight prep: fp16 fragments (col-major [n,k]) from W[c][d].
// ---------------------------------------------------------------------------
__global__ void wprep_kernel(const float* __restrict__ W1b,
                             const float* __restrict__ W2b) {
    const int nt = blockIdx.x, kc = blockIdx.y, L = blockIdx.z;
    const int l  = threadIdx.x;
    const float* W = L ? W2b : W1b;
    const int n  = nt * 8 + (l >> 2);
    const int k0 = kc * 16 + (l & 3) * 2;

    float v[4];
    v[0] = W[(k0 + 0) * NH + n];
    v[1] = W[(k0 + 1) * NH + n];
    v[2] = W[(k0 + 8) * NH + n];
    v[3] = W[(k0 + 9) * NH + n];
    const int idx = (nt * 8 + kc) * 32 + l;
    g_wfh[L][idx] = make_uint2(pack_h2(v[0], v[1]), pack_h2(v[2], v[3]));
}

// ---------------------------------------------------------------------------
// Edge-conv layer via mma.sync fp16 (single term, fp32 accumulate).
// CTA = 8 points = 128 edges. A (acts) fp16 in one 32KB swizzled smem tile.
// ---------------------------------------------------------------------------
template <int MODE>
__global__ __launch_bounds__(128) void layer_mma(
    const float* __restrict__ pos,
    const float* __restrict__ Wsmall,   // MODE1: W1a[6,128]; MODE2: W2a rows 128..130
    const float* __restrict__ bh,       // MODE1: b1a
    const float* __restrict__ bo)       // out bias
{
    extern __shared__ char dsm[];
    __shared__ float sM[8][KK][6];
    __shared__ int   sJ[8][KK];

    const int tid = threadIdx.x;
    const int wid = tid >> 5, lid = tid & 31;
    const int p0  = blockIdx.x * 8;
    const int L   = MODE - 1;

    char* actH = (char*)(((uintptr_t)dsm + 1023) & ~(uintptr_t)1023);

    // ---- neighbor / message prep: thread -> (pt = tid>>4, k = tid&15) ------
    {
        const int pt = tid >> 4, k = tid & 15;
        const int p  = p0 + pt;
        const int b  = p / PP;
        const int jg = b * PP + g_nbr[p * KK + k];
        sJ[pt][k] = jg;
        const float pjx = pos[jg * 3 + 0], pjy = pos[jg * 3 + 1], pjz = pos[jg * 3 + 2];
        const float pix = pos[p * 3 + 0],  piy = pos[p * 3 + 1],  piz = pos[p * 3 + 2];
        if (MODE == 1) {
            sM[pt][k][0] = pjx; sM[pt][k][1] = pjy; sM[pt][k][2] = pjz;
            sM[pt][k][3] = pjx - pix; sM[pt][k][4] = pjy - piy; sM[pt][k][5] = pjz - piz;
        } else {
            sM[pt][k][0] = pjx - pix; sM[pt][k][1] = pjy - piy; sM[pt][k][2] = pjz - piz;
        }
    }
    __syncthreads();

    // ---- Stage A: warp w builds edges 32w..32w+31; lane owns dims 4l..4l+3 -
    {
        const int d0 = lid * 4;
        float4 wsm4[6];
        const int NSM = (MODE == 1) ? 6 : 3;
#pragma unroll
        for (int u = 0; u < 6; ++u)
            wsm4[u] = (u < NSM) ? *(const float4*)&Wsmall[u * NH + d0]
                                : make_float4(0.f, 0.f, 0.f, 0.f);
        float4 bh4 = make_float4(0.f, 0.f, 0.f, 0.f);
        if (MODE == 1) bh4 = *(const float4*)&bh[d0];

        const uint32_t lane_off = (((uint32_t)(lid >> 1)) << 4) + ((lid & 1) << 3);

#pragma unroll 4
        for (int i = 0; i < 32; ++i) {
            const int e  = wid * 32 + i;
            const int pt = e >> 4, k = e & 15;
            float h0, h1, h2, h3;
            if (MODE == 1) {
                h0 = bh4.x; h1 = bh4.y; h2 = bh4.z; h3 = bh4.w;
#pragma unroll
                for (int u = 0; u < 6; ++u) {
                    const float mu = sM[pt][k][u];
                    h0 = fmaf(mu, wsm4[u].x, h0);
                    h1 = fmaf(mu, wsm4[u].y, h1);
                    h2 = fmaf(mu, wsm4[u].z, h2);
                    h3 = fmaf(mu, wsm4[u].w, h3);
                }
            } else {
                const float4 t4 = *(const float4*)&g_t[(size_t)sJ[pt][k] * NH + d0];
                h0 = t4.x; h1 = t4.y; h2 = t4.z; h3 = t4.w;
#pragma unroll
                for (int u = 0; u < 3; ++u) {
                    const float mu = sM[pt][k][u];
                    h0 = fmaf(mu, wsm4[u].x, h0);
                    h1 = fmaf(mu, wsm4[u].y, h1);
                    h2 = fmaf(mu, wsm4[u].z, h2);
                    h3 = fmaf(mu, wsm4[u].w, h3);
                }
            }
            h0 = fmaxf(h0, 0.f); h1 = fmaxf(h1, 0.f);
            h2 = fmaxf(h2, 0.f); h3 = fmaxf(h3, 0.f);

            // row e layout: byte(d) = e*256 + (((d>>3)^(e&7))<<4) + ((d*2)&15)
            const uint32_t off = (uint32_t)e * 256 +
                                 (lane_off ^ (((uint32_t)(e & 7)) << 4));
            *(uint2*)(actH + off) = make_uint2(pack_h2(h0, h1), pack_h2(h2, h3));
        }
    }
    __syncthreads();

    // ---- GEMM (kc outer, mt inner) + max epilogue --------------------------
    float* dst = (MODE == 1) ? g_h1 : g_h2;
    const uint32_t aHs = smem_u32(actH);
    const int rowl  = (lid & 15);
    const int koffl = ((lid >> 4) & 1) * 16;

#pragma unroll
    for (int g = 0; g < 2; ++g) {
        const int nt0 = wid * 4 + g * 2;

        float acc[8][2][4];
#pragma unroll
        for (int mt = 0; mt < 8; ++mt)
#pragma unroll
            for (int t = 0; t < 2; ++t)
#pragma unroll
                for (int c = 0; c < 4; ++c) acc[mt][t][c] = 0.f;

#pragma unroll
        for (int kc = 0; kc < 8; ++kc) {
            const uint2 bH0 = g_wfh[L][((nt0 + 0) * 8 + kc) * 32 + lid];
            const uint2 bH1 = g_wfh[L][((nt0 + 1) * 8 + kc) * 32 + lid];
            const int kx = kc * 2 + (koffl >> 4);

#pragma unroll
            for (int mt = 0; mt < 8; ++mt) {
                const int r = mt * 16 + rowl;
                const uint32_t off = ((uint32_t)r << 8) +
                                     ((uint32_t)(kx ^ (r & 7)) << 4);
                uint32_t ah[4];
                ldsm_x4(ah, aHs + off);
                mma_f16(acc[mt][0], ah, bH0);
                mma_f16(acc[mt][1], ah, bH1);
            }
        }

        // epilogue: max over 16 edge rows per point, bias, relu, store
#pragma unroll
        for (int mt = 0; mt < 8; ++mt) {
            const int p = p0 + mt;
#pragma unroll
            for (int t = 0; t < 2; ++t) {
                float c0 = fmaxf(acc[mt][t][0], acc[mt][t][2]);
                float c1 = fmaxf(acc[mt][t][1], acc[mt][t][3]);
#pragma unroll
                for (int s = 4; s <= 16; s <<= 1) {
                    c0 = fmaxf(c0, __shfl_xor_sync(0xffffffffu, c0, s));
                    c1 = fmaxf(c1, __shfl_xor_sync(0xffffffffu, c1, s));
                }
                if (lid < 4) {
                    const int n0 = (nt0 + t) * 8 + 2 * lid;
                    const float2 bv = *(const float2*)&bo[n0];
                    float2 o;
                    o.x = fmaxf(c0 + bv.x, 0.f);
                    o.y = fmaxf(c1 + bv.y, 0.f);
                    *(float2*)&dst[(size_t)p * NH + n0] = o;
                }
            }
        }
    }
}

// ---------------------------------------------------------------------------
// t-precompute: g_t[r] = g_h1[r] @ W2a[0:128] + b2a (fp32, f32x2 packed).
// ---------------------------------------------------------------------------
__global__ __launch_bounds__(128) void tprep_kernel(
    const float* __restrict__ Wb, const float* __restrict__ bo)
{
    __shared__ __align__(16) float hid[16][NH];
    const int tid = threadIdx.x;
    const int wid = tid >> 5, lid = tid & 31;
    const int row0 = blockIdx.x * 16;

#pragma unroll
    for (int r = 0; r < 16; ++r)
        hid[r][tid] = g_h1[(size_t)(row0 + r) * NH + tid];
    __syncthreads();

    const int rb = wid * 4;
    const int d0 = lid * 4;

    u64 acc[4][2];
#pragma unroll
    for (int r = 0; r < 4; ++r) { acc[r][0] = 0ULL; acc[r][1] = 0ULL; }

#pragma unroll 2
    for (int c = 0; c < NH; c += 4) {
        const ulonglong2 wa  = *(const ulonglong2*)&Wb[(c + 0) * NH + d0];
        const ulonglong2 wb2 = *(const ulonglong2*)&Wb[(c + 1) * NH + d0];
        const ulonglong2 wc2 = *(const ulonglong2*)&Wb[(c + 2) * NH + d0];
        const ulonglong2 wd2 = *(const ulonglong2*)&Wb[(c + 3) * NH + d0];
#pragma unroll
        for (int r = 0; r < 4; ++r) {
            const float4 h4 = *(const float4*)&hid[rb + r][c];
            const u64 h0 = pack_dup(h4.x);
            const u64 h1 = pack_dup(h4.y);
            const u64 h2 = pack_dup(h4.z);
            const u64 h3 = pack_dup(h4.w);
            acc[r][0] = ffma2(h0, wa.x,  acc[r][0]);
            acc[r][1] = ffma2(h0, wa.y,  acc[r][1]);
            acc[r][0] = ffma2(h1, wb2.x, acc[r][0]);
            acc[r][1] = ffma2(h1, wb2.y, acc[r][1]);
            acc[r][0] = ffma2(h2, wc2.x, acc[r][0]);
            acc[r][1] = ffma2(h2, wc2.y, acc[r][1]);
            acc[r][0] = ffma2(h3, wd2.x, acc[r][0]);
            acc[r][1] = ffma2(h3, wd2.y, acc[r][1]);
        }
    }

    const float4 bv = *(const float4*)&bo[d0];
#pragma unroll
    for (int r = 0; r < 4; ++r) {
        const float2 f0 = unpack2(acc[r][0]);
        const float2 f1 = unpack2(acc[r][1]);
        float4 o;
        o.x = f0.x + bv.x; o.y = f0.y + bv.y;
        o.z = f1.x + bv.z; o.w = f1.y + bv.w;
        *(float4*)&g_t[(size_t)(row0 + rb + r) * NH + d0] = o;
    }
}

// ---------------------------------------------------------------------------
// Global max pool + classifier
// ---------------------------------------------------------------------------
__global__ void pool_kernel(const float* __restrict__ Wc,
                            const float* __restrict__ bc,
                            float* __restrict__ out) {
    const int b   = blockIdx.x;
    const int tid = threadIdx.x;
    const float* hb = g_h2 + (size_t)b * PP * NH;

    float m0 = -3.4e38f, m1 = m0, m2 = m0, m3 = m0;
    for (int p = 0; p < PP; p += 4) {
        m0 = fmaxf(m0, hb[(size_t)(p + 0) * NH + tid]);
        m1 = fmaxf(m1, hb[(size_t)(p + 1) * NH + tid]);
        m2 = fmaxf(m2, hb[(size_t)(p + 2) * NH + tid]);
        m3 = fmaxf(m3, hb[(size_t)(p + 3) * NH + tid]);
    }
    __shared__ float sg[NH];
    sg[tid] = fmaxf(fmaxf(m0, m1), fmaxf(m2, m3));
    __syncthreads();

    if (tid < 10) {
        float a = bc[tid];
#pragma unroll 8
        for (int d = 0; d < NH; ++d) a = fmaf(sg[d], Wc[d * 10 + tid], a);
        out[b * 10 + tid] = a;
    }
}

// ---------------------------------------------------------------------------
extern "C" void kernel_launch(void* const* d_in, const int* in_sizes, int n_in,
                              void* d_out, int out_size) {
    const float* pos = (const float*)d_in[0];
    const float* W1a = (const float*)d_in[2];
    const float* b1a = (const float*)d_in[3];
    const float* W1b = (const float*)d_in[4];
    const float* b1b = (const float*)d_in[5];
    const float* W2a = (const float*)d_in[6];
    const float* b2a = (const float*)d_in[7];
    const float* W2b = (const float*)d_in[8];
    const float* b2b = (const float*)d_in[9];
    const float* Wc  = (const float*)d_in[10];
    const float* bc  = (const float*)d_in[11];
    float* out = (float*)d_out;

    const int DSM = 32768 + 1024;   // single fp16 act tile + alignment pad
    cudaFuncSetAttribute(layer_mma<1>, cudaFuncAttributeMaxDynamicSharedMemorySize, DSM);
    cudaFuncSetAttribute(layer_mma<2>, cudaFuncAttributeMaxDynamicSharedMemorySize, DSM);

    knn_kernel<<<dim3(PP / 128, BB), 128>>>(pos);
    wprep_kernel<<<dim3(16, 8, 2), 32>>>(W1b, W2b);
    layer_mma<1><<<BB * PP / 8, 128, DSM>>>(pos, W1a, b1a, b1b);
    tprep_kernel<<<BB * PP / 16, 128>>>(W2a, b2a);
    layer_mma<2><<<BB * PP / 8, 128, DSM>>>(pos, W2a + 128 * NH, nullptr, b2b);
    pool_kernel<<<BB, 128>>>(Wc, bc, out);
}

// round 10
// speedup vs baseline: 3.3658x; 1.0579x over previous
#include <cuda_runtime.h>
#include <cuda_fp16.h>
#include <math.h>
#include <stdint.h>

#define BB 32
#define PP 2048
#define KK 16
#define NH 128

// Scratch (no allocations allowed).
__device__ int   g_nbr[BB * PP * KK];
__device__ float g_t [BB * PP * NH];
__device__ float g_h2[BB * PP * NH];
// Weight fragments (fp16) in mma B register order:
// [mat][(nt*8+kc)*32+lane] -> uint2{b0,b1};  mat: 0=W1b, 1=W2b, 2=W2a[0:128]
__device__ uint2 g_wfh[3][16 * 8 * 32];

// ---- helpers ---------------------------------------------------------------
__device__ __forceinline__ uint32_t smem_u32(const void* p) {
    return (uint32_t)__cvta_generic_to_shared(p);
}
__device__ __forceinline__ uint32_t pack_h2(float a, float b) {
    const __half2 h = __floats2half2_rn(a, b);
    return *(const uint32_t*)&h;
}
__device__ __forceinline__ void ldsm_x4(uint32_t* r, uint32_t addr) {
    asm volatile("ldmatrix.sync.aligned.m8n8.x4.shared.b16 {%0,%1,%2,%3}, [%4];"
                 : "=r"(r[0]), "=r"(r[1]), "=r"(r[2]), "=r"(r[3]) : "r"(addr));
}
__device__ __forceinline__ void mma_f16(float* d, const uint32_t* a, uint2 b) {
    asm volatile(
        "mma.sync.aligned.m16n8k16.row.col.f32.f16.f16.f32 "
        "{%0,%1,%2,%3}, {%4,%5,%6,%7}, {%8,%9}, {%0,%1,%2,%3};"
        : "+f"(d[0]), "+f"(d[1]), "+f"(d[2]), "+f"(d[3])
        : "r"(a[0]), "r"(a[1]), "r"(a[2]), "r"(a[3]), "r"(b.x), "r"(b.y));
}

// ---------------------------------------------------------------------------
// KNN (unchanged, known-correct)
// ---------------------------------------------------------------------------
__global__ void knn_kernel(const float* __restrict__ pos) {
    const int b = blockIdx.y;
    const int q = blockIdx.x * blockDim.x + threadIdx.x;
    const float* pb = pos + (size_t)b * PP * 3;

    const float qx = pb[q * 3 + 0];
    const float qy = pb[q * 3 + 1];
    const float qz = pb[q * 3 + 2];
    const float qsq = qx * qx + qy * qy + qz * qz;

    float kd[KK];
    int   ki[KK];
#pragma unroll
    for (int s = 0; s < KK; ++s) { kd[s] = 3.4e38f; ki[s] = -1; }

    __shared__ float4 tile[128];

    for (int t0 = 0; t0 < PP; t0 += 128) {
        const int j = t0 + threadIdx.x;
        const float x = pb[j * 3 + 0];
        const float y = pb[j * 3 + 1];
        const float z = pb[j * 3 + 2];
        tile[threadIdx.x] = make_float4(x, y, z, x * x + y * y + z * z);
        __syncthreads();

#pragma unroll 4
        for (int jj = 0; jj < 128; ++jj) {
            const float4 c = tile[jj];
            const float dot = qx * c.x + qy * c.y + qz * c.z;
            const float d2  = (qsq + c.w) - 2.0f * dot;
            if (d2 < kd[KK - 1]) {
                kd[KK - 1] = d2;
                ki[KK - 1] = t0 + jj;
#pragma unroll
                for (int s = KK - 1; s > 0; --s) {
                    if (kd[s] < kd[s - 1]) {
                        const float td = kd[s]; kd[s] = kd[s - 1]; kd[s - 1] = td;
                        const int   ti = ki[s]; ki[s] = ki[s - 1]; ki[s - 1] = ti;
                    }
                }
            }
        }
        __syncthreads();
    }

    const int base = (b * PP + q) * KK;
#pragma unroll
    for (int s = 0; s < KK; ++s) g_nbr[base + s] = ki[s];
}

// ---------------------------------------------------------------------------
// Weight prep: fp16 fragments (col-major [n,k]) for W1b, W2b, W2a[0:128].
// ---------------------------------------------------------------------------
__global__ void wprep_kernel(const float* __restrict__ W1b,
                             const float* __restrict__ W2b,
                             const float* __restrict__ W2a) {
    const int nt = blockIdx.x, kc = blockIdx.y, L = blockIdx.z;
    const int l  = threadIdx.x;
    const float* W = (L == 0) ? W1b : ((L == 1) ? W2b : W2a);
    const int n  = nt * 8 + (l >> 2);
    const int k0 = kc * 16 + (l & 3) * 2;

    float v[4];
    v[0] = W[(k0 + 0) * NH + n];
    v[1] = W[(k0 + 1) * NH + n];
    v[2] = W[(k0 + 8) * NH + n];
    v[3] = W[(k0 + 9) * NH + n];
    const int idx = (nt * 8 + kc) * 32 + l;
    g_wfh[L][idx] = make_uint2(pack_h2(v[0], v[1]), pack_h2(v[2], v[3]));
}

// ---------------------------------------------------------------------------
// Edge-conv layer via mma.sync fp16 (fp32 accumulate). CTA = 8 pts = 128 edges.
// GEMM: 4 n-tiles fused per A-fragment (64 ldsm/warp). MODE1 additionally
// computes t = h1 @ W2a + b2a in-kernel (mini-MMA) and writes only g_t.
// ---------------------------------------------------------------------------
template <int MODE>
__global__ __launch_bounds__(128) void layer_mma(
    const float* __restrict__ pos,
    const float* __restrict__ Wsmall,   // MODE1: W1a[6,128]; MODE2: W2a rows 128..130
    const float* __restrict__ bh,       // MODE1: b1a
    const float* __restrict__ bo,       // MODE1: b1b; MODE2: b2b
    const float* __restrict__ b2a)      // MODE1 only
{
    extern __shared__ char dsm[];
    __shared__ float sM[8][KK][6];
    __shared__ int   sJ[8][KK];

    const int tid = threadIdx.x;
    const int wid = tid >> 5, lid = tid & 31;
    const int p0  = blockIdx.x * 8;
    const int L   = MODE - 1;

    char* actH = (char*)(((uintptr_t)dsm + 1023) & ~(uintptr_t)1023);
    char* h1t  = actH + 32768;          // MODE1: 4KB fp16 h1 tile (16 rows x 128)

    // MODE1: zero h1 tile rows 8-15 (bytes [2048,4096))
    if (MODE == 1)
        *(uint4*)(h1t + 2048 + tid * 16) = make_uint4(0u, 0u, 0u, 0u);

    // ---- neighbor / message prep: thread -> (pt = tid>>4, k = tid&15) ------
    {
        const int pt = tid >> 4, k = tid & 15;
        const int p  = p0 + pt;
        const int b  = p / PP;
        const int jg = b * PP + g_nbr[p * KK + k];
        sJ[pt][k] = jg;
        const float pjx = pos[jg * 3 + 0], pjy = pos[jg * 3 + 1], pjz = pos[jg * 3 + 2];
        const float pix = pos[p * 3 + 0],  piy = pos[p * 3 + 1],  piz = pos[p * 3 + 2];
        if (MODE == 1) {
            sM[pt][k][0] = pjx; sM[pt][k][1] = pjy; sM[pt][k][2] = pjz;
            sM[pt][k][3] = pjx - pix; sM[pt][k][4] = pjy - piy; sM[pt][k][5] = pjz - piz;
        } else {
            sM[pt][k][0] = pjx - pix; sM[pt][k][1] = pjy - piy; sM[pt][k][2] = pjz - piz;
        }
    }
    __syncthreads();

    // ---- Stage A: warp w builds edges 32w..32w+31; lane owns dims 4l..4l+3 -
    {
        const int d0 = lid * 4;
        float4 wsm4[6];
        const int NSM = (MODE == 1) ? 6 : 3;
#pragma unroll
        for (int u = 0; u < 6; ++u)
            wsm4[u] = (u < NSM) ? *(const float4*)&Wsmall[u * NH + d0]
                                : make_float4(0.f, 0.f, 0.f, 0.f);
        float4 bh4 = make_float4(0.f, 0.f, 0.f, 0.f);
        if (MODE == 1) bh4 = *(const float4*)&bh[d0];

        const uint32_t lane_off = (((uint32_t)(lid >> 1)) << 4) + ((lid & 1) << 3);

#pragma unroll 4
        for (int i = 0; i < 32; ++i) {
            const int e  = wid * 32 + i;
            const int pt = e >> 4, k = e & 15;
            float h0, h1, h2, h3;
            if (MODE == 1) {
                h0 = bh4.x; h1 = bh4.y; h2 = bh4.z; h3 = bh4.w;
#pragma unroll
                for (int u = 0; u < 6; ++u) {
                    const float mu = sM[pt][k][u];
                    h0 = fmaf(mu, wsm4[u].x, h0);
                    h1 = fmaf(mu, wsm4[u].y, h1);
                    h2 = fmaf(mu, wsm4[u].z, h2);
                    h3 = fmaf(mu, wsm4[u].w, h3);
                }
            } else {
                const float4 t4 = *(const float4*)&g_t[(size_t)sJ[pt][k] * NH + d0];
                h0 = t4.x; h1 = t4.y; h2 = t4.z; h3 = t4.w;
#pragma unroll
                for (int u = 0; u < 3; ++u) {
                    const float mu = sM[pt][k][u];
                    h0 = fmaf(mu, wsm4[u].x, h0);
                    h1 = fmaf(mu, wsm4[u].y, h1);
                    h2 = fmaf(mu, wsm4[u].z, h2);
                    h3 = fmaf(mu, wsm4[u].w, h3);
                }
            }
            h0 = fmaxf(h0, 0.f); h1 = fmaxf(h1, 0.f);
            h2 = fmaxf(h2, 0.f); h3 = fmaxf(h3, 0.f);

            // row e layout: byte(d) = e*256 + (((d>>3)^(e&7))<<4) + ((d*2)&15)
            const uint32_t off = (uint32_t)e * 256 +
                                 (lane_off ^ (((uint32_t)(e & 7)) << 4));
            *(uint2*)(actH + off) = make_uint2(pack_h2(h0, h1), pack_h2(h2, h3));
        }
    }
    __syncthreads();

    // ---- GEMM: mt-half outer, 4 n-tiles fused per A-fragment ---------------
    const uint32_t aHs = smem_u32(actH);
    const int rowl  = (lid & 15);
    const int kxofs = (lid >> 4) & 1;

#pragma unroll
    for (int mh = 0; mh < 2; ++mh) {
        float acc[4][4][4];
#pragma unroll
        for (int mt = 0; mt < 4; ++mt)
#pragma unroll
            for (int j = 0; j < 4; ++j)
#pragma unroll
                for (int c = 0; c < 4; ++c) acc[mt][j][c] = 0.f;

#pragma unroll
        for (int kc = 0; kc < 8; ++kc) {
            uint2 bf[4];
#pragma unroll
            for (int j = 0; j < 4; ++j)
                bf[j] = g_wfh[L][((wid * 4 + j) * 8 + kc) * 32 + lid];
            const int kx = kc * 2 + kxofs;

#pragma unroll
            for (int mt = 0; mt < 4; ++mt) {
                const int r = (mh * 4 + mt) * 16 + rowl;
                const uint32_t off = ((uint32_t)r << 8) +
                                     ((uint32_t)(kx ^ (r & 7)) << 4);
                uint32_t ah[4];
                ldsm_x4(ah, aHs + off);
                mma_f16(acc[mt][0], ah, bf[0]);
                mma_f16(acc[mt][1], ah, bf[1]);
                mma_f16(acc[mt][2], ah, bf[2]);
                mma_f16(acc[mt][3], ah, bf[3]);
            }
        }

        // epilogue: max over 16 edge rows per point, bias, relu
#pragma unroll
        for (int mt = 0; mt < 4; ++mt) {
            const int prow = mh * 4 + mt;            // point index in CTA
#pragma unroll
            for (int j = 0; j < 4; ++j) {
                float c0 = fmaxf(acc[mt][j][0], acc[mt][j][2]);
                float c1 = fmaxf(acc[mt][j][1], acc[mt][j][3]);
#pragma unroll
                for (int s = 4; s <= 16; s <<= 1) {
                    c0 = fmaxf(c0, __shfl_xor_sync(0xffffffffu, c0, s));
                    c1 = fmaxf(c1, __shfl_xor_sync(0xffffffffu, c1, s));
                }
                if (lid < 4) {
                    const int nt = wid * 4 + j;
                    const int n0 = nt * 8 + 2 * lid;
                    const float2 bv = *(const float2*)&bo[n0];
                    const float o0 = fmaxf(c0 + bv.x, 0.f);
                    const float o1 = fmaxf(c1 + bv.y, 0.f);
                    if (MODE == 1) {
                        // h1 -> fp16 smem tile (row = prow, cols n0,n0+1)
                        const uint32_t hoff = (uint32_t)prow * 256 +
                            ((uint32_t)(nt ^ prow) << 4) + (uint32_t)(4 * lid);
                        *(uint32_t*)(h1t + hoff) = pack_h2(o0, o1);
                    } else {
                        *(float2*)&g_h2[(size_t)(p0 + prow) * NH + n0] =
                            make_float2(o0, o1);
                    }
                }
            }
        }
    }

    // ---- MODE1 mini-GEMM: t[8,128] = h1[8,128] @ W2a[0:128] + b2a ----------
    if (MODE == 1) {
        __syncthreads();
        const uint32_t h1s = smem_u32(h1t);
        float acc2[4][4];
#pragma unroll
        for (int j = 0; j < 4; ++j)
#pragma unroll
            for (int c = 0; c < 4; ++c) acc2[j][c] = 0.f;

#pragma unroll
        for (int kc = 0; kc < 8; ++kc) {
            const int kx = kc * 2 + kxofs;
            const uint32_t off = ((uint32_t)rowl << 8) +
                                 ((uint32_t)(kx ^ (rowl & 7)) << 4);
            uint32_t ah[4];
            ldsm_x4(ah, h1s + off);
#pragma unroll
            for (int j = 0; j < 4; ++j) {
                const uint2 bf = g_wfh[2][((wid * 4 + j) * 8 + kc) * 32 + lid];
                mma_f16(acc2[j], ah, bf);
            }
        }

        // store rows 0-7 (d0,d1 -> row = lid>>2, cols 2*(lid&3)+{0,1})
        const int row = lid >> 2;
#pragma unroll
        for (int j = 0; j < 4; ++j) {
            const int n0 = (wid * 4 + j) * 8 + 2 * (lid & 3);
            const float2 bv = *(const float2*)&b2a[n0];
            *(float2*)&g_t[(size_t)(p0 + row) * NH + n0] =
                make_float2(acc2[j][0] + bv.x, acc2[j][1] + bv.y);
        }
    }
}

// ---------------------------------------------------------------------------
// Global max pool + classifier
// ---------------------------------------------------------------------------
__global__ void pool_kernel(const float* __restrict__ Wc,
                            const float* __restrict__ bc,
                            float* __restrict__ out) {
    const int b   = blockIdx.x;
    const int tid = threadIdx.x;
    const float* hb = g_h2 + (size_t)b * PP * NH;

    float m0 = -3.4e38f, m1 = m0, m2 = m0, m3 = m0;
    for (int p = 0; p < PP; p += 4) {
        m0 = fmaxf(m0, hb[(size_t)(p + 0) * NH + tid]);
        m1 = fmaxf(m1, hb[(size_t)(p + 1) * NH + tid]);
        m2 = fmaxf(m2, hb[(size_t)(p + 2) * NH + tid]);
        m3 = fmaxf(m3, hb[(size_t)(p + 3) * NH + tid]);
    }
    __shared__ float sg[NH];
    sg[tid] = fmaxf(fmaxf(m0, m1), fmaxf(m2, m3));
    __syncthreads();

    if (tid < 10) {
        float a = bc[tid];
#pragma unroll 8
        for (int d = 0; d < NH; ++d) a = fmaf(sg[d], Wc[d * 10 + tid], a);
        out[b * 10 + tid] = a;
    }
}

// ---------------------------------------------------------------------------
extern "C" void kernel_launch(void* const* d_in, const int* in_sizes, int n_in,
                              void* d_out, int out_size) {
    const float* pos = (const float*)d_in[0];
    const float* W1a = (const float*)d_in[2];
    const float* b1a = (const float*)d_in[3];
    const float* W1b = (const float*)d_in[4];
    const float* b1b = (const float*)d_in[5];
    const float* W2a = (const float*)d_in[6];
    const float* b2a = (const float*)d_in[7];
    const float* W2b = (const float*)d_in[8];
    const float* b2b = (const float*)d_in[9];
    const float* Wc  = (const float*)d_in[10];
    const float* bc  = (const float*)d_in[11];
    float* out = (float*)d_out;

    const int DSM = 32768 + 4096 + 1024;  // act tile + h1 tile + alignment pad
    cudaFuncSetAttribute(layer_mma<1>, cudaFuncAttributeMaxDynamicSharedMemorySize, DSM);
    cudaFuncSetAttribute(layer_mma<2>, cudaFuncAttributeMaxDynamicSharedMemorySize, DSM);

    knn_kernel<<<dim3(PP / 128, BB), 128>>>(pos);
    wprep_kernel<<<dim3(16, 8, 3), 32>>>(W1b, W2b, W2a);
    layer_mma<1><<<BB * PP / 8, 128, DSM>>>(pos, W1a, b1a, b1b, b2a);
    layer_mma<2><<<BB * PP / 8, 128, DSM>>>(pos, W2a + 128 * NH, nullptr, b2b, nullptr);
    pool_kernel<<<BB, 128>>>(Wc, bc, out);
}

// round 11
// speedup vs baseline: 4.4246x; 1.3146x over previous
#include <cuda_runtime.h>
#include <cuda_fp16.h>
#include <math.h>
#include <stdint.h>

#define BB 32
#define PP 2048
#define KK 16
#define NH 128
#define KNN_CAP 24

typedef unsigned long long u64;

// Scratch (no allocations allowed).
__device__ int   g_nbr[BB * PP * KK];
__device__ float g_t [BB * PP * NH];
__device__ float g_h2[BB * PP * NH];
__device__ float g_part[BB][8][NH];
// Weight fragments (fp16) in mma B register order:
// [mat][(nt*8+kc)*32+lane] -> uint2{b0,b1};  mat: 0=W1b, 1=W2b, 2=W2a[0:128]
__device__ uint2 g_wfh[3][16 * 8 * 32];

// ---- helpers ---------------------------------------------------------------
__device__ __forceinline__ uint32_t smem_u32(const void* p) {
    return (uint32_t)__cvta_generic_to_shared(p);
}
__device__ __forceinline__ uint32_t pack_h2(float a, float b) {
    const __half2 h = __floats2half2_rn(a, b);
    return *(const uint32_t*)&h;
}
__device__ __forceinline__ void ldsm_x4(uint32_t* r, uint32_t addr) {
    asm volatile("ldmatrix.sync.aligned.m8n8.x4.shared.b16 {%0,%1,%2,%3}, [%4];"
                 : "=r"(r[0]), "=r"(r[1]), "=r"(r[2]), "=r"(r[3]) : "r"(addr));
}
__device__ __forceinline__ void mma_f16(float* d, const uint32_t* a, uint2 b) {
    asm volatile(
        "mma.sync.aligned.m16n8k16.row.col.f32.f16.f16.f32 "
        "{%0,%1,%2,%3}, {%4,%5,%6,%7}, {%8,%9}, {%0,%1,%2,%3};"
        : "+f"(d[0]), "+f"(d[1]), "+f"(d[2]), "+f"(d[3])
        : "r"(a[0]), "r"(a[1]), "r"(a[2]), "r"(a[3]), "r"(b.x), "r"(b.y));
}

// ---------------------------------------------------------------------------
// KNN with deferred-batched insertion. Exact: same accept set & order as the
// classic sorted-insert (stale threshold only over-accepts; chain filters).
// ---------------------------------------------------------------------------
__global__ void knn_kernel(const float* __restrict__ pos) {
    __shared__ float4 tile[128];
    __shared__ u64 buf[128][KNN_CAP];

    const int tid = threadIdx.x;
    const int b = blockIdx.y;
    const int q = blockIdx.x * blockDim.x + tid;
    const float* pb = pos + (size_t)b * PP * 3;

    const float qx = pb[q * 3 + 0];
    const float qy = pb[q * 3 + 1];
    const float qz = pb[q * 3 + 2];
    const float qsq = qx * qx + qy * qy + qz * qz;

    float kd[KK];
    int   ki[KK];
#pragma unroll
    for (int s = 0; s < KK; ++s) { kd[s] = 3.4e38f; ki[s] = -1; }

    float T = 3.4e38f;
    int cnt = 0;

#define CHAIN_INSERT(dd, jj2)                                                  \
    do {                                                                       \
        kd[KK - 1] = (dd); ki[KK - 1] = (jj2);                                 \
        _Pragma("unroll")                                                      \
        for (int s = KK - 1; s > 0; --s) {                                     \
            if (kd[s] < kd[s - 1]) {                                           \
                const float td = kd[s]; kd[s] = kd[s - 1]; kd[s - 1] = td;     \
                const int   ti = ki[s]; ki[s] = ki[s - 1]; ki[s - 1] = ti;     \
            }                                                                  \
        }                                                                      \
    } while (0)

#define FLUSH_BUF()                                                            \
    do {                                                                       \
        for (int i = 0; i < cnt; ++i) {                                        \
            const u64 kk = buf[tid][i];                                        \
            const float dd = __uint_as_float((uint32_t)(kk >> 32));            \
            const int jj2 = (int)(kk & 0xffffffffu);                           \
            if (dd < kd[KK - 1]) CHAIN_INSERT(dd, jj2);                        \
        }                                                                      \
        cnt = 0; T = kd[KK - 1];                                               \
    } while (0)

    for (int t0 = 0; t0 < PP; t0 += 128) {
        const int j = t0 + tid;
        const float x = pb[j * 3 + 0];
        const float y = pb[j * 3 + 1];
        const float z = pb[j * 3 + 2];
        tile[tid] = make_float4(x, y, z, x * x + y * y + z * z);
        __syncthreads();

        if (t0 == 0) {
            // classic insertion for the first tile -> tight threshold
#pragma unroll 4
            for (int jj = 0; jj < 128; ++jj) {
                const float4 c = tile[jj];
                const float dot = qx * c.x + qy * c.y + qz * c.z;
                const float d2  = (qsq + c.w) - 2.0f * dot;
                if (d2 < kd[KK - 1]) CHAIN_INSERT(d2, jj);
            }
            T = kd[KK - 1];
        } else {
#pragma unroll 4
            for (int jj = 0; jj < 128; ++jj) {
                const float4 c = tile[jj];
                const float dot = qx * c.x + qy * c.y + qz * c.z;
                const float d2  = (qsq + c.w) - 2.0f * dot;
                if (d2 < T) {
                    if (cnt == KNN_CAP) FLUSH_BUF();   // rare inline overflow
                    buf[tid][cnt++] =
                        ((u64)__float_as_uint(d2) << 32) | (uint32_t)(t0 + jj);
                }
            }
            FLUSH_BUF();   // batched: warp cost = max-lane count, dense work
        }
        __syncthreads();
    }

    const int base = (b * PP + q) * KK;
#pragma unroll
    for (int s = 0; s < KK; ++s) g_nbr[base + s] = ki[s];
#undef CHAIN_INSERT
#undef FLUSH_BUF
}

// ---------------------------------------------------------------------------
// Weight prep (one matrix per launch): fp16 fragments (col-major [n,k]).
// ---------------------------------------------------------------------------
__global__ void wprep_kernel(const float* __restrict__ W, int L) {
    const int nt = blockIdx.x, kc = blockIdx.y;
    const int l  = threadIdx.x;
    const int n  = nt * 8 + (l >> 2);
    const int k0 = kc * 16 + (l & 3) * 2;

    float v[4];
    v[0] = W[(k0 + 0) * NH + n];
    v[1] = W[(k0 + 1) * NH + n];
    v[2] = W[(k0 + 8) * NH + n];
    v[3] = W[(k0 + 9) * NH + n];
    const int idx = (nt * 8 + kc) * 32 + l;
    g_wfh[L][idx] = make_uint2(pack_h2(v[0], v[1]), pack_h2(v[2], v[3]));
}

// ---------------------------------------------------------------------------
// Edge-conv layer via mma.sync fp16 (fp32 accumulate). CTA = 8 pts = 128 edges.
// GEMM: 4 n-tiles fused per A-fragment. MODE1 additionally computes
// t = h1 @ W2a + b2a in-kernel (mini-MMA) and writes only g_t.
// ---------------------------------------------------------------------------
template <int MODE>
__global__ __launch_bounds__(128, 5) void layer_mma(
    const float* __restrict__ pos,
    const float* __restrict__ Wsmall,   // MODE1: W1a[6,128]; MODE2: W2a rows 128..130
    const float* __restrict__ bh,       // MODE1: b1a
    const float* __restrict__ bo,       // MODE1: b1b; MODE2: b2b
    const float* __restrict__ b2a)      // MODE1 only
{
    extern __shared__ char dsm[];
    __shared__ float sM[8][KK][6];
    __shared__ int   sJ[8][KK];

    const int tid = threadIdx.x;
    const int wid = tid >> 5, lid = tid & 31;
    const int p0  = blockIdx.x * 8;
    const int L   = MODE - 1;

    char* actH = (char*)(((uintptr_t)dsm + 1023) & ~(uintptr_t)1023);
    char* h1t  = actH + 32768;          // MODE1: 4KB fp16 h1 tile (16 rows x 128)

    // MODE1: zero h1 tile rows 8-15 (bytes [2048,4096))
    if (MODE == 1)
        *(uint4*)(h1t + 2048 + tid * 16) = make_uint4(0u, 0u, 0u, 0u);

    // ---- neighbor / message prep: thread -> (pt = tid>>4, k = tid&15) ------
    {
        const int pt = tid >> 4, k = tid & 15;
        const int p  = p0 + pt;
        const int b  = p / PP;
        const int jg = b * PP + g_nbr[p * KK + k];
        sJ[pt][k] = jg;
        const float pjx = pos[jg * 3 + 0], pjy = pos[jg * 3 + 1], pjz = pos[jg * 3 + 2];
        const float pix = pos[p * 3 + 0],  piy = pos[p * 3 + 1],  piz = pos[p * 3 + 2];
        if (MODE == 1) {
            sM[pt][k][0] = pjx; sM[pt][k][1] = pjy; sM[pt][k][2] = pjz;
            sM[pt][k][3] = pjx - pix; sM[pt][k][4] = pjy - piy; sM[pt][k][5] = pjz - piz;
        } else {
            sM[pt][k][0] = pjx - pix; sM[pt][k][1] = pjy - piy; sM[pt][k][2] = pjz - piz;
        }
    }
    __syncthreads();

    // ---- Stage A: warp w builds edges 32w..32w+31; lane owns dims 4l..4l+3 -
    {
        const int d0 = lid * 4;
        float4 wsm4[6];
        const int NSM = (MODE == 1) ? 6 : 3;
#pragma unroll
        for (int u = 0; u < 6; ++u)
            wsm4[u] = (u < NSM) ? *(const float4*)&Wsmall[u * NH + d0]
                                : make_float4(0.f, 0.f, 0.f, 0.f);
        float4 bh4 = make_float4(0.f, 0.f, 0.f, 0.f);
        if (MODE == 1) bh4 = *(const float4*)&bh[d0];

        const uint32_t lane_off = (((uint32_t)(lid >> 1)) << 4) + ((lid & 1) << 3);

#pragma unroll 4
        for (int i = 0; i < 32; ++i) {
            const int e  = wid * 32 + i;
            const int pt = e >> 4, k = e & 15;
            float h0, h1, h2, h3;
            if (MODE == 1) {
                h0 = bh4.x; h1 = bh4.y; h2 = bh4.z; h3 = bh4.w;
#pragma unroll
                for (int u = 0; u < 6; ++u) {
                    const float mu = sM[pt][k][u];
                    h0 = fmaf(mu, wsm4[u].x, h0);
                    h1 = fmaf(mu, wsm4[u].y, h1);
                    h2 = fmaf(mu, wsm4[u].z, h2);
                    h3 = fmaf(mu, wsm4[u].w, h3);
                }
            } else {
                const float4 t4 = *(const float4*)&g_t[(size_t)sJ[pt][k] * NH + d0];
                h0 = t4.x; h1 = t4.y; h2 = t4.z; h3 = t4.w;
#pragma unroll
                for (int u = 0; u < 3; ++u) {
                    const float mu = sM[pt][k][u];
                    h0 = fmaf(mu, wsm4[u].x, h0);
                    h1 = fmaf(mu, wsm4[u].y, h1);
                    h2 = fmaf(mu, wsm4[u].z, h2);
                    h3 = fmaf(mu, wsm4[u].w, h3);
                }
            }
            h0 = fmaxf(h0, 0.f); h1 = fmaxf(h1, 0.f);
            h2 = fmaxf(h2, 0.f); h3 = fmaxf(h3, 0.f);

            // row e layout: byte(d) = e*256 + (((d>>3)^(e&7))<<4) + ((d*2)&15)
            const uint32_t off = (uint32_t)e * 256 +
                                 (lane_off ^ (((uint32_t)(e & 7)) << 4));
            *(uint2*)(actH + off) = make_uint2(pack_h2(h0, h1), pack_h2(h2, h3));
        }
    }
    __syncthreads();

    // ---- GEMM: mt-half outer, 4 n-tiles fused per A-fragment ---------------
    const uint32_t aHs = smem_u32(actH);
    const int rowl  = (lid & 15);
    const int kxofs = (lid >> 4) & 1;

#pragma unroll
    for (int mh = 0; mh < 2; ++mh) {
        float acc[4][4][4];
#pragma unroll
        for (int mt = 0; mt < 4; ++mt)
#pragma unroll
            for (int j = 0; j < 4; ++j)
#pragma unroll
                for (int c = 0; c < 4; ++c) acc[mt][j][c] = 0.f;

#pragma unroll
        for (int kc = 0; kc < 8; ++kc) {
            uint2 bf[4];
#pragma unroll
            for (int j = 0; j < 4; ++j)
                bf[j] = g_wfh[L][((wid * 4 + j) * 8 + kc) * 32 + lid];
            const int kx = kc * 2 + kxofs;

#pragma unroll
            for (int mt = 0; mt < 4; ++mt) {
                const int r = (mh * 4 + mt) * 16 + rowl;
                const uint32_t off = ((uint32_t)r << 8) +
                                     ((uint32_t)(kx ^ (r & 7)) << 4);
                uint32_t ah[4];
                ldsm_x4(ah, aHs + off);
                mma_f16(acc[mt][0], ah, bf[0]);
                mma_f16(acc[mt][1], ah, bf[1]);
                mma_f16(acc[mt][2], ah, bf[2]);
                mma_f16(acc[mt][3], ah, bf[3]);
            }
        }

        // epilogue: max over 16 edge rows per point, bias, relu
#pragma unroll
        for (int mt = 0; mt < 4; ++mt) {
            const int prow = mh * 4 + mt;            // point index in CTA
#pragma unroll
            for (int j = 0; j < 4; ++j) {
                float c0 = fmaxf(acc[mt][j][0], acc[mt][j][2]);
                float c1 = fmaxf(acc[mt][j][1], acc[mt][j][3]);
#pragma unroll
                for (int s = 4; s <= 16; s <<= 1) {
                    c0 = fmaxf(c0, __shfl_xor_sync(0xffffffffu, c0, s));
                    c1 = fmaxf(c1, __shfl_xor_sync(0xffffffffu, c1, s));
                }
                if (lid < 4) {
                    const int nt = wid * 4 + j;
                    const int n0 = nt * 8 + 2 * lid;
                    const float2 bv = *(const float2*)&bo[n0];
                    const float o0 = fmaxf(c0 + bv.x, 0.f);
                    const float o1 = fmaxf(c1 + bv.y, 0.f);
                    if (MODE == 1) {
                        // h1 -> fp16 smem tile (row = prow, cols n0,n0+1)
                        const uint32_t hoff = (uint32_t)prow * 256 +
                            ((uint32_t)(nt ^ prow) << 4) + (uint32_t)(4 * lid);
                        *(uint32_t*)(h1t + hoff) = pack_h2(o0, o1);
                    } else {
                        *(float2*)&g_h2[(size_t)(p0 + prow) * NH + n0] =
                            make_float2(o0, o1);
                    }
                }
            }
        }
    }

    // ---- MODE1 mini-GEMM: t[8,128] = h1[8,128] @ W2a[0:128] + b2a ----------
    if (MODE == 1) {
        __syncthreads();
        const uint32_t h1s = smem_u32(h1t);
        float acc2[4][4];
#pragma unroll
        for (int j = 0; j < 4; ++j)
#pragma unroll
            for (int c = 0; c < 4; ++c) acc2[j][c] = 0.f;

#pragma unroll
        for (int kc = 0; kc < 8; ++kc) {
            const int kx = kc * 2 + kxofs;
            const uint32_t off = ((uint32_t)rowl << 8) +
                                 ((uint32_t)(kx ^ (rowl & 7)) << 4);
            uint32_t ah[4];
            ldsm_x4(ah, h1s + off);
#pragma unroll
            for (int j = 0; j < 4; ++j) {
                const uint2 bf = g_wfh[2][((wid * 4 + j) * 8 + kc) * 32 + lid];
                mma_f16(acc2[j], ah, bf);
            }
        }

        // store rows 0-7 (d0,d1 -> row = lid>>2, cols 2*(lid&3)+{0,1})
        const int row = lid >> 2;
#pragma unroll
        for (int j = 0; j < 4; ++j) {
            const int n0 = (wid * 4 + j) * 8 + 2 * (lid & 3);
            const float2 bv = *(const float2*)&b2a[n0];
            *(float2*)&g_t[(size_t)(p0 + row) * NH + n0] =
                make_float2(acc2[j][0] + bv.x, acc2[j][1] + bv.y);
        }
    }
}

// ---------------------------------------------------------------------------
// Pool stage 1: partial max over 256-point segments.
// ---------------------------------------------------------------------------
__global__ void pool1_kernel() {
    const int b = blockIdx.y, seg = blockIdx.x;
    const int tid = threadIdx.x;
    const float* hb = g_h2 + ((size_t)b * PP + seg * 256) * NH;

    float m0 = -3.4e38f, m1 = m0, m2 = m0, m3 = m0;
    for (int p = 0; p < 256; p += 4) {
        m0 = fmaxf(m0, hb[(size_t)(p + 0) * NH + tid]);
        m1 = fmaxf(m1, hb[(size_t)(p + 1) * NH + tid]);
        m2 = fmaxf(m2, hb[(size_t)(p + 2) * NH + tid]);
        m3 = fmaxf(m3, hb[(size_t)(p + 3) * NH + tid]);
    }
    g_part[b][seg][tid] = fmaxf(fmaxf(m0, m1), fmaxf(m2, m3));
}

// ---------------------------------------------------------------------------
// Pool stage 2: combine partials + classifier.
// ---------------------------------------------------------------------------
__global__ void pool2_kernel(const float* __restrict__ Wc,
                             const float* __restrict__ bc,
                             float* __restrict__ out) {
    const int b   = blockIdx.x;
    const int tid = threadIdx.x;

    float m = g_part[b][0][tid];
#pragma unroll
    for (int s = 1; s < 8; ++s) m = fmaxf(m, g_part[b][s][tid]);

    __shared__ float sg[NH];
    sg[tid] = m;
    __syncthreads();

    if (tid < 10) {
        float a = bc[tid];
#pragma unroll 8
        for (int d = 0; d < NH; ++d) a = fmaf(sg[d], Wc[d * 10 + tid], a);
        out[b * 10 + tid] = a;
    }
}

// ---------------------------------------------------------------------------
extern "C" void kernel_launch(void* const* d_in, const int* in_sizes, int n_in,
                              void* d_out, int out_size) {
    const float* pos = (const float*)d_in[0];
    const float* W1a = (const float*)d_in[2];
    const float* b1a = (const float*)d_in[3];
    const float* W1b = (const float*)d_in[4];
    const float* b1b = (const float*)d_in[5];
    const float* W2a = (const float*)d_in[6];
    const float* b2a = (const float*)d_in[7];
    const float* W2b = (const float*)d_in[8];
    const float* b2b = (const float*)d_in[9];
    const float* Wc  = (const float*)d_in[10];
    const float* bc  = (const float*)d_in[11];
    float* out = (float*)d_out;

    const int DSM1 = 32768 + 4096 + 1024;  // act tile + h1 tile + pad
    const int DSM2 = 32768 + 1024;         // act tile + pad
    cudaFuncSetAttribute(layer_mma<1>, cudaFuncAttributeMaxDynamicSharedMemorySize, DSM1);
    cudaFuncSetAttribute(layer_mma<2>, cudaFuncAttributeMaxDynamicSharedMemorySize, DSM2);

    // wprep split into 3 launches (also positions knn as the 4th launch for ncu)
    wprep_kernel<<<dim3(16, 8), 32>>>(W1b, 0);
    wprep_kernel<<<dim3(16, 8), 32>>>(W2b, 1);
    wprep_kernel<<<dim3(16, 8), 32>>>(W2a, 2);
    knn_kernel<<<dim3(PP / 128, BB), 128>>>(pos);
    layer_mma<1><<<BB * PP / 8, 128, DSM1>>>(pos, W1a, b1a, b1b, b2a);
    layer_mma<2><<<BB * PP / 8, 128, DSM2>>>(pos, W2a + 128 * NH, nullptr, b2b, nullptr);
    pool1_kernel<<<dim3(8, BB), 128>>>();
    pool2_kernel<<<BB, 128>>>(Wc, bc, out);
}